// round 3
// baseline (speedup 1.0000x reference)
#include <cuda_runtime.h>
#include <math.h>

// ---------------- problem constants ----------------
#define BATCH 4
#define C1    64
#define H1    224
#define W1    224
#define C2    128
#define H2    112
#define W2    112
#define HP    114          // padded height for deform gather
#define WP    114
#define HW2   (H2*W2)      // 12544
#define COFF  18

// ---------------- scratch (__device__ globals; no allocation) ----------------
__device__ float g_h1[BATCH*C1*H1*W1];        // relu(conv1+bias)
__device__ float g_pool[BATCH*C1*H2*W2];      // BN1-affine + 2x2 avgpool
__device__ float g_h2[BATCH*C2*H2*W2];        // relu(conv2+bias)
__device__ float g_h2n[BATCH*C2*H2*W2];       // BN2 normalized (unpadded)
__device__ float g_h2pad[BATCH*C2*HP*WP];     // BN2 normalized, zero-padded 114x114
__device__ float g_offs[BATCH*COFF*H2*W2];    // offsets conv output
__device__ float g_scale1[C1], g_shift1[C1];
__device__ float g_scale2[C2], g_shift2[C2];

// ---------------- generic 3x3 conv, pad=1, stride=1, NCHW fp32 ----------------
// 16x16 output tile, 128 threads (each thread: 2 vertical pixels x OC_T channels)
template<int IC_CHUNK, int OC_T, bool RELU>
__global__ void __launch_bounds__(128)
conv3x3_kernel(const float* __restrict__ in, const float* __restrict__ wgt,
               const float* __restrict__ bias, float* __restrict__ out,
               int C_in, int C_out, int H, int W, int tilesW)
{
    const int TW = 16, TH = 16;
    __shared__ float s_in[IC_CHUNK][TH+2][TW+2];
    __shared__ float s_w [OC_T][IC_CHUNK][9];

    const int tileIdx = blockIdx.x;
    const int tileX   = (tileIdx % tilesW) * TW;
    const int tileY   = (tileIdx / tilesW) * TH;
    const int ocBase  = blockIdx.y * OC_T;
    const int b       = blockIdx.z;
    const int tid     = threadIdx.x;
    const int tx      = tid & 15;
    const int ty      = tid >> 4;          // 0..7 (2 rows each)

    float acc0[OC_T], acc1[OC_T];
#pragma unroll
    for (int i = 0; i < OC_T; i++) { acc0[i] = 0.f; acc1[i] = 0.f; }

    for (int ic0 = 0; ic0 < C_in; ic0 += IC_CHUNK) {
        // cooperative input tile load (zero outside)
        for (int e = tid; e < IC_CHUNK*(TH+2)*(TW+2); e += 128) {
            int ic = e / ((TH+2)*(TW+2));
            int r  = (e / (TW+2)) % (TH+2);
            int c  = e % (TW+2);
            int gy = tileY + r - 1, gx = tileX + c - 1;
            float v = 0.f;
            if (gy >= 0 && gy < H && gx >= 0 && gx < W)
                v = in[(((size_t)b*C_in + ic0+ic)*H + gy)*W + gx];
            s_in[ic][r][c] = v;
        }
        // weight chunk load
        for (int e = tid; e < OC_T*IC_CHUNK*9; e += 128) {
            int oc = e / (IC_CHUNK*9);
            int rem = e % (IC_CHUNK*9);
            int ic = rem / 9, k = rem % 9;
            s_w[oc][ic][k] = wgt[((size_t)(ocBase+oc)*C_in + ic0+ic)*9 + k];
        }
        __syncthreads();

        const int y0 = ty * 2;
#pragma unroll 4
        for (int ic = 0; ic < IC_CHUNK; ic++) {
            float r[4][3];
#pragma unroll
            for (int rr = 0; rr < 4; rr++)
#pragma unroll
                for (int cc = 0; cc < 3; cc++)
                    r[rr][cc] = s_in[ic][y0+rr][tx+cc];
#pragma unroll
            for (int oc = 0; oc < OC_T; oc++) {
                float a0 = acc0[oc], a1 = acc1[oc];
#pragma unroll
                for (int k = 0; k < 9; k++) {
                    float wv = s_w[oc][ic][k];
                    a0 = fmaf(r[k/3  ][k%3], wv, a0);
                    a1 = fmaf(r[k/3+1][k%3], wv, a1);
                }
                acc0[oc] = a0; acc1[oc] = a1;
            }
        }
        __syncthreads();
    }

    const int gy0 = tileY + ty*2;
    const int gx  = tileX + tx;
#pragma unroll
    for (int oc = 0; oc < OC_T; oc++) {
        float bv = bias ? bias[ocBase+oc] : 0.f;
        float v0 = acc0[oc] + bv, v1 = acc1[oc] + bv;
        if (RELU) { v0 = fmaxf(v0, 0.f); v1 = fmaxf(v1, 0.f); }
        size_t base = (((size_t)b*C_out + ocBase+oc)*H + gy0)*W + gx;
        out[base]     = v0;
        out[base + W] = v1;
    }
}

// ---------------- BN stats (per channel over B*H*W) -> folded scale/shift ----------------
__global__ void __launch_bounds__(256)
bn_stats_kernel(const float* __restrict__ in, const float* __restrict__ gamma,
                const float* __restrict__ beta, float* __restrict__ scale,
                float* __restrict__ shift, int C, int HW)
{
    const int c = blockIdx.x;
    const int tid = threadIdx.x;
    float s = 0.f, ss = 0.f;
    for (int b = 0; b < BATCH; b++) {
        const float* p = in + ((size_t)b*C + c)*HW;
        for (int i = tid; i < HW; i += 256) { float v = p[i]; s += v; ss += v*v; }
    }
    __shared__ float sh[64];
#pragma unroll
    for (int o = 16; o; o >>= 1) {
        s  += __shfl_down_sync(0xffffffffu, s,  o);
        ss += __shfl_down_sync(0xffffffffu, ss, o);
    }
    int warp = tid >> 5, lane = tid & 31;
    if (lane == 0) { sh[warp] = s; sh[32+warp] = ss; }
    __syncthreads();
    if (warp == 0) {
        s  = (lane < 8) ? sh[lane]    : 0.f;
        ss = (lane < 8) ? sh[32+lane] : 0.f;
#pragma unroll
        for (int o = 4; o; o >>= 1) {
            s  += __shfl_down_sync(0xffffffffu, s,  o);
            ss += __shfl_down_sync(0xffffffffu, ss, o);
        }
        if (lane == 0) {
            float n    = (float)(BATCH) * (float)HW;
            float mean = s / n;
            float var  = ss / n - mean*mean;
            float inv  = rsqrtf(var + 1e-5f);
            float sc   = gamma[c] * inv;
            scale[c] = sc;
            shift[c] = beta[c] - mean * sc;
        }
    }
}

// ---------------- BN1 affine + 2x2 avg pool ----------------
__global__ void __launch_bounds__(256)
pool_bn_kernel()
{
    int idx = blockIdx.x * 256 + threadIdx.x;
    const int total = BATCH*C1*H2*W2;
    if (idx >= total) return;
    int w = idx % W2;
    int h = (idx / W2) % H2;
    int c = (idx / (W2*H2)) % C1;
    int b = idx / (W2*H2*C1);
    const float* p = g_h1 + (((size_t)b*C1 + c)*H1 + 2*h)*W1 + 2*w;
    float v = 0.25f * (p[0] + p[1] + p[W1] + p[W1+1]);
    g_pool[idx] = v * g_scale1[c] + g_shift1[c];
}

// ---------------- BN2 apply -> unpadded + zero-padded planes ----------------
__global__ void __launch_bounds__(256)
bn2_apply_kernel()
{
    int idx = blockIdx.x * 256 + threadIdx.x;
    const int total = BATCH*C2*HP*WP;
    if (idx >= total) return;
    int pw = idx % WP;
    int ph = (idx / WP) % HP;
    int c  = (idx / (WP*HP)) % C2;
    int b  = idx / (WP*HP*C2);
    float v = 0.f;
    if (ph >= 1 && ph <= H2 && pw >= 1 && pw <= W2) {
        size_t off = (((size_t)b*C2 + c)*H2 + (ph-1))*W2 + (pw-1);
        v = g_h2[off] * g_scale2[c] + g_shift2[c];
        g_h2n[off] = v;
    }
    g_h2pad[idx] = v;
}

// ---------------- deformable conv: per-32-pixel-tile GEMM ----------------
// out[b,oc,hw] = sum_{ic,n} w4[oc,ic,n] * bilinear(h2pad[b,ic], pos(b,n,hw))
__global__ void __launch_bounds__(256)
deform_kernel(const float* __restrict__ w4, float* __restrict__ out)
{
    __shared__ int                  s_idx[4][9][32];
    __shared__ float                s_bw [4][9][32];
    __shared__ __align__(16) float  s_xo [4][9][32];   // [icr][n][px]
    __shared__ float                s_wt [128][37];    // [oc][icr*9+n], pad vs bank conflicts

    const int tid  = threadIdx.x;
    const int px0  = blockIdx.x * 32;
    const int b    = px0 / HW2;          // tiles never cross batch (12544 % 32 == 0)
    const int hw0  = px0 % HW2;

    // Phase 0: bilinear params per (n, pixel), shared across all 128 channels
    for (int e = tid; e < 288; e += 256) {
        int n = e >> 5, p = e & 31;
        int hw = hw0 + p;
        int h = hw / W2, w = hw % W2;
        float ox = g_offs[((size_t)b*COFF + n)     * HW2 + hw];
        float oy = g_offs[((size_t)b*COFF + 9 + n) * HW2 + hw];
        float pX = (float)(h + 1) + (float)(n/3 - 1) + ox;
        float pY = (float)(w + 1) + (float)(n%3 - 1) + oy;
        float fx = floorf(pX), fy = floorf(pY);
        float qltx = fminf(fmaxf(fx,      0.f), (float)(HP-1));
        float qlty = fminf(fmaxf(fy,      0.f), (float)(WP-1));
        float qrbx = fminf(fmaxf(fx+1.f,  0.f), (float)(HP-1));
        float qrby = fminf(fmaxf(fy+1.f,  0.f), (float)(WP-1));
        bool mx = (pX < 1.f) || (pX > (float)(HP-2));
        bool my = (pY < 1.f) || (pY > (float)(WP-2));
        float pxc = fminf(fmaxf(mx ? fx : pX, 0.f), (float)(HP-1));
        float pyc = fminf(fmaxf(my ? fy : pY, 0.f), (float)(WP-1));
        float glt = (1.f + (qltx - pxc)) * (1.f + (qlty - pyc));
        float grb = (1.f - (qrbx - pxc)) * (1.f - (qrby - pyc));
        float glb = (1.f + (qltx - pxc)) * (1.f - (qrby - pyc));
        float grt = (1.f - (qrbx - pxc)) * (1.f + (qlty - pyc));
        int ix0 = (int)qltx, iy0 = (int)qlty;
        int ix1 = (int)qrbx, iy1 = (int)qrby;
        s_idx[0][n][p] = ix0*WP + iy0;  s_bw[0][n][p] = glt;
        s_idx[1][n][p] = ix1*WP + iy1;  s_bw[1][n][p] = grb;
        s_idx[2][n][p] = ix0*WP + iy1;  s_bw[2][n][p] = glb;
        s_idx[3][n][p] = ix1*WP + iy0;  s_bw[3][n][p] = grt;
    }

    float acc[4][4] = {};
    const int pxg = tid & 7;   // pixel group: px = pxg*4 + j
    const int ocg = tid >> 3;  // oc group:    oc = ocg*4 + i

    for (int ic0 = 0; ic0 < C2; ic0 += 4) {
        __syncthreads();  // also covers phase0 -> first chunk
        // produce x_off slab for 4 input channels
        for (int e = tid; e < 4*288; e += 256) {
            int icr = e / 288;
            int rem = e % 288;
            int n = rem >> 5, p = rem & 31;
            const float* plane = g_h2pad + ((size_t)(b*C2 + ic0 + icr))*HP*WP;
            float v = s_bw[0][n][p] * __ldg(plane + s_idx[0][n][p])
                    + s_bw[1][n][p] * __ldg(plane + s_idx[1][n][p])
                    + s_bw[2][n][p] * __ldg(plane + s_idx[2][n][p])
                    + s_bw[3][n][p] * __ldg(plane + s_idx[3][n][p]);
            s_xo[icr][n][p] = v;
        }
        // weight slab: [oc][icr*9+n]
        for (int e = tid; e < 128*36; e += 256) {
            int oc = e / 36, r = e % 36;
            int icr = r / 9, n = r % 9;
            s_wt[oc][r] = w4[((size_t)oc*C2 + ic0 + icr)*9 + n];
        }
        __syncthreads();

        // register-tiled GEMM: 4 oc x 4 px per thread
#pragma unroll
        for (int r = 0; r < 36; r++) {
            const int icr = r / 9, n = r % 9;
            float4 bv = ((const float4*)(&s_xo[icr][n][0]))[pxg];
            float a0 = s_wt[ocg*4+0][r];
            float a1 = s_wt[ocg*4+1][r];
            float a2 = s_wt[ocg*4+2][r];
            float a3 = s_wt[ocg*4+3][r];
            acc[0][0] = fmaf(a0, bv.x, acc[0][0]);
            acc[0][1] = fmaf(a0, bv.y, acc[0][1]);
            acc[0][2] = fmaf(a0, bv.z, acc[0][2]);
            acc[0][3] = fmaf(a0, bv.w, acc[0][3]);
            acc[1][0] = fmaf(a1, bv.x, acc[1][0]);
            acc[1][1] = fmaf(a1, bv.y, acc[1][1]);
            acc[1][2] = fmaf(a1, bv.z, acc[1][2]);
            acc[1][3] = fmaf(a1, bv.w, acc[1][3]);
            acc[2][0] = fmaf(a2, bv.x, acc[2][0]);
            acc[2][1] = fmaf(a2, bv.y, acc[2][1]);
            acc[2][2] = fmaf(a2, bv.z, acc[2][2]);
            acc[2][3] = fmaf(a2, bv.w, acc[2][3]);
            acc[3][0] = fmaf(a3, bv.x, acc[3][0]);
            acc[3][1] = fmaf(a3, bv.y, acc[3][1]);
            acc[3][2] = fmaf(a3, bv.z, acc[3][2]);
            acc[3][3] = fmaf(a3, bv.w, acc[3][3]);
        }
    }

    // epilogue: float4 stores, coalesced per oc
#pragma unroll
    for (int i = 0; i < 4; i++) {
        int oc = ocg*4 + i;
        float4 v = make_float4(acc[i][0], acc[i][1], acc[i][2], acc[i][3]);
        *(float4*)(out + ((size_t)b*C2 + oc)*HW2 + hw0 + pxg*4) = v;
    }
}

// ---------------- launch ----------------
extern "C" void kernel_launch(void* const* d_in, const int* in_sizes, int n_in,
                              void* d_out, int out_size)
{
    const float* x       = (const float*)d_in[0];
    const float* conv1_w = (const float*)d_in[1];
    const float* conv1_b = (const float*)d_in[2];
    const float* bn1_g   = (const float*)d_in[3];
    const float* bn1_b   = (const float*)d_in[4];
    const float* conv2_w = (const float*)d_in[5];
    const float* conv2_b = (const float*)d_in[6];
    const float* bn2_g   = (const float*)d_in[7];
    const float* bn2_b   = (const float*)d_in[8];
    const float* off_w   = (const float*)d_in[9];
    const float* off_b   = (const float*)d_in[10];
    const float* conv4_w = (const float*)d_in[11];
    float* out = (float*)d_out;

    float *p_h1, *p_pool, *p_h2, *p_h2n, *p_offs, *p_s1, *p_t1, *p_s2, *p_t2;
    cudaGetSymbolAddress((void**)&p_h1,   g_h1);
    cudaGetSymbolAddress((void**)&p_pool, g_pool);
    cudaGetSymbolAddress((void**)&p_h2,   g_h2);
    cudaGetSymbolAddress((void**)&p_h2n,  g_h2n);
    cudaGetSymbolAddress((void**)&p_offs, g_offs);
    cudaGetSymbolAddress((void**)&p_s1,   g_scale1);
    cudaGetSymbolAddress((void**)&p_t1,   g_shift1);
    cudaGetSymbolAddress((void**)&p_s2,   g_scale2);
    cudaGetSymbolAddress((void**)&p_t2,   g_shift2);

    // 1) conv1 + bias + relu : 4x3x224x224 -> 4x64x224x224
    {
        dim3 grid(14*14, C1/8, BATCH);
        conv3x3_kernel<3, 8, true><<<grid, 128>>>(x, conv1_w, conv1_b, p_h1,
                                                  3, C1, H1, W1, 14);
    }
    // 2) BN1 stats
    bn_stats_kernel<<<C1, 256>>>(p_h1, bn1_g, bn1_b, p_s1, p_t1, C1, H1*W1);
    // 3) BN1 affine + 2x2 avgpool -> 4x64x112x112
    pool_bn_kernel<<<(BATCH*C1*H2*W2)/256, 256>>>();
    // 4) conv2 + bias + relu : -> 4x128x112x112
    {
        dim3 grid(7*7, C2/8, BATCH);
        conv3x3_kernel<16, 8, true><<<grid, 128>>>(p_pool, conv2_w, conv2_b, p_h2,
                                                   C1, C2, H2, W2, 7);
    }
    // 5) BN2 stats
    bn_stats_kernel<<<C2, 256>>>(p_h2, bn2_g, bn2_b, p_s2, p_t2, C2, H2*W2);
    // 6) BN2 apply -> g_h2n (unpadded) + g_h2pad (zero border)
    bn2_apply_kernel<<<(BATCH*C2*HP*WP)/256, 256>>>();
    // 7) offsets conv : 128 -> 18 (+bias, no relu)
    {
        dim3 grid(7*7, COFF/6, BATCH);
        conv3x3_kernel<16, 6, false><<<grid, 128>>>(p_h2n, off_w, off_b, p_offs,
                                                    C2, COFF, H2, W2, 7);
    }
    // 8) deformable conv -> d_out 4x128x112x112
    deform_kernel<<<(BATCH*HW2)/32, 256>>>(conv4_w, out);
}

// round 4
// speedup vs baseline: 1.0006x; 1.0006x over previous
#include <cuda_runtime.h>
#include <math.h>

// ---------------- problem constants ----------------
#define BATCH 4
#define C1    64
#define H1    224
#define W1    224
#define C2    128
#define H2    112
#define W2    112
#define HP    114          // padded height/width
#define WP    114
#define HW2   (H2*W2)      // 12544
#define HWP   (HP*WP)      // 12996
#define COFF  18

// ---------------- scratch (__device__ globals; no allocation) ----------------
__device__ float g_h1[BATCH*C1*H1*W1];        // relu(conv1+bias)
__device__ float g_poolpad[BATCH*C1*HWP];     // BN1-affine + 2x2 avgpool, zero-padded
__device__ float g_h2[BATCH*C2*H2*W2];        // relu(conv2+bias)
__device__ float g_h2pad[BATCH*C2*HWP];       // BN2 normalized, zero-padded
__device__ float g_offs[BATCH*COFF*HW2];      // offsets conv output
__device__ float g_wt2T[C1*9*C2];             // conv2 weights transposed [ic*9+n][oc]
__device__ float g_wt4T[C2*9*C2];             // conv4 weights transposed [ic*9+n][oc]
__device__ float g_scale1[C1], g_shift1[C1];
__device__ float g_scale2[C2], g_shift2[C2];

// ---------------- weight transpose: w[oc][ic][9] -> wT[ic*9+n][oc] ----------------
__global__ void __launch_bounds__(256)
transpose_w_kernel(const float* __restrict__ w, float* __restrict__ wT,
                   int C_in, int C_out)
{
    int idx = blockIdx.x * 256 + threadIdx.x;
    int total = C_out * C_in * 9;
    if (idx >= total) return;
    int oc = idx % C_out;
    int r  = idx / C_out;      // ic*9+n
    int ic = r / 9, n = r % 9;
    wT[idx] = w[((size_t)oc*C_in + ic)*9 + n];
}

// ---------------- generic 3x3 conv (bounds-checked input), for conv1 ----------------
template<int IC_CHUNK, int OC_T, bool RELU>
__global__ void __launch_bounds__(128)
conv3x3_kernel(const float* __restrict__ in, const float* __restrict__ wgt,
               const float* __restrict__ bias, float* __restrict__ out,
               int C_in, int C_out, int H, int W, int tilesW)
{
    const int TW = 16, TH = 16;
    __shared__ float s_in[IC_CHUNK][TH+2][TW+2];
    __shared__ float s_w [OC_T][IC_CHUNK][9];

    const int tileIdx = blockIdx.x;
    const int tileX   = (tileIdx % tilesW) * TW;
    const int tileY   = (tileIdx / tilesW) * TH;
    const int ocBase  = blockIdx.y * OC_T;
    const int b       = blockIdx.z;
    const int tid     = threadIdx.x;
    const int tx      = tid & 15;
    const int ty      = tid >> 4;

    float acc0[OC_T], acc1[OC_T];
#pragma unroll
    for (int i = 0; i < OC_T; i++) { acc0[i] = 0.f; acc1[i] = 0.f; }

    for (int ic0 = 0; ic0 < C_in; ic0 += IC_CHUNK) {
        for (int e = tid; e < IC_CHUNK*(TH+2)*(TW+2); e += 128) {
            int ic = e / ((TH+2)*(TW+2));
            int r  = (e / (TW+2)) % (TH+2);
            int c  = e % (TW+2);
            int gy = tileY + r - 1, gx = tileX + c - 1;
            float v = 0.f;
            if (gy >= 0 && gy < H && gx >= 0 && gx < W)
                v = in[(((size_t)b*C_in + ic0+ic)*H + gy)*W + gx];
            s_in[ic][r][c] = v;
        }
        for (int e = tid; e < OC_T*IC_CHUNK*9; e += 128) {
            int oc = e / (IC_CHUNK*9);
            int rem = e % (IC_CHUNK*9);
            int ic = rem / 9, k = rem % 9;
            s_w[oc][ic][k] = wgt[((size_t)(ocBase+oc)*C_in + ic0+ic)*9 + k];
        }
        __syncthreads();

        const int y0 = ty * 2;
#pragma unroll
        for (int ic = 0; ic < IC_CHUNK; ic++) {
            float r[4][3];
#pragma unroll
            for (int rr = 0; rr < 4; rr++)
#pragma unroll
                for (int cc = 0; cc < 3; cc++)
                    r[rr][cc] = s_in[ic][y0+rr][tx+cc];
#pragma unroll
            for (int oc = 0; oc < OC_T; oc++) {
                float a0 = acc0[oc], a1 = acc1[oc];
#pragma unroll
                for (int k = 0; k < 9; k++) {
                    float wv = s_w[oc][ic][k];
                    a0 = fmaf(r[k/3  ][k%3], wv, a0);
                    a1 = fmaf(r[k/3+1][k%3], wv, a1);
                }
                acc0[oc] = a0; acc1[oc] = a1;
            }
        }
        __syncthreads();
    }

    const int gy0 = tileY + ty*2;
    const int gx  = tileX + tx;
#pragma unroll
    for (int oc = 0; oc < OC_T; oc++) {
        float bv = bias ? bias[ocBase+oc] : 0.f;
        float v0 = acc0[oc] + bv, v1 = acc1[oc] + bv;
        if (RELU) { v0 = fmaxf(v0, 0.f); v1 = fmaxf(v1, 0.f); }
        size_t base = (((size_t)b*C_out + ocBase+oc)*H + gy0)*W + gx;
        out[base]     = v0;
        out[base + W] = v1;
    }
}

// ---------------- 3x3 conv reading a zero-padded (H+2)x(W+2) plane, for offsets ----------------
template<int IC_CHUNK, int OC_T>
__global__ void __launch_bounds__(128)
conv3x3_pad_kernel(const float* __restrict__ in, const float* __restrict__ wgt,
                   const float* __restrict__ bias, float* __restrict__ out,
                   int C_in, int C_out, int H, int W, int tilesW)
{
    const int TW = 16, TH = 16;
    const int Hp = H + 2, Wp = W + 2;
    __shared__ float s_in[IC_CHUNK][TH+2][TW+2];
    __shared__ float s_w [OC_T][IC_CHUNK][9];

    const int tileIdx = blockIdx.x;
    const int tileX   = (tileIdx % tilesW) * TW;
    const int tileY   = (tileIdx / tilesW) * TH;
    const int ocBase  = blockIdx.y * OC_T;
    const int b       = blockIdx.z;
    const int tid     = threadIdx.x;
    const int tx      = tid & 15;
    const int ty      = tid >> 4;

    float acc0[OC_T], acc1[OC_T];
#pragma unroll
    for (int i = 0; i < OC_T; i++) { acc0[i] = 0.f; acc1[i] = 0.f; }

    for (int ic0 = 0; ic0 < C_in; ic0 += IC_CHUNK) {
        for (int e = tid; e < IC_CHUNK*(TH+2)*(TW+2); e += 128) {
            int ic = e / ((TH+2)*(TW+2));
            int r  = (e / (TW+2)) % (TH+2);
            int c  = e % (TW+2);
            s_in[ic][r][c] =
                in[(((size_t)b*C_in + ic0+ic)*Hp + tileY + r)*Wp + tileX + c];
        }
        for (int e = tid; e < OC_T*IC_CHUNK*9; e += 128) {
            int oc = e / (IC_CHUNK*9);
            int rem = e % (IC_CHUNK*9);
            int ic = rem / 9, k = rem % 9;
            s_w[oc][ic][k] = wgt[((size_t)(ocBase+oc)*C_in + ic0+ic)*9 + k];
        }
        __syncthreads();

        const int y0 = ty * 2;
#pragma unroll
        for (int ic = 0; ic < IC_CHUNK; ic++) {
            float r[4][3];
#pragma unroll
            for (int rr = 0; rr < 4; rr++)
#pragma unroll
                for (int cc = 0; cc < 3; cc++)
                    r[rr][cc] = s_in[ic][y0+rr][tx+cc];
#pragma unroll
            for (int oc = 0; oc < OC_T; oc++) {
                float a0 = acc0[oc], a1 = acc1[oc];
#pragma unroll
                for (int k = 0; k < 9; k++) {
                    float wv = s_w[oc][ic][k];
                    a0 = fmaf(r[k/3  ][k%3], wv, a0);
                    a1 = fmaf(r[k/3+1][k%3], wv, a1);
                }
                acc0[oc] = a0; acc1[oc] = a1;
            }
        }
        __syncthreads();
    }

    const int gy0 = tileY + ty*2;
    const int gx  = tileX + tx;
#pragma unroll
    for (int oc = 0; oc < OC_T; oc++) {
        float bv = bias[ocBase+oc];
        size_t base = (((size_t)b*C_out + ocBase+oc)*H + gy0)*W + gx;
        out[base]     = acc0[oc] + bv;
        out[base + W] = acc1[oc] + bv;
    }
}

// ---------------- BN stats -> folded scale/shift ----------------
__global__ void __launch_bounds__(256)
bn_stats_kernel(const float* __restrict__ in, const float* __restrict__ gamma,
                const float* __restrict__ beta, float* __restrict__ scale,
                float* __restrict__ shift, int C, int HW)
{
    const int c = blockIdx.x;
    const int tid = threadIdx.x;
    float s = 0.f, ss = 0.f;
    for (int b = 0; b < BATCH; b++) {
        const float* p = in + ((size_t)b*C + c)*HW;
        for (int i = tid; i < HW; i += 256) { float v = p[i]; s += v; ss += v*v; }
    }
    __shared__ float sh[64];
#pragma unroll
    for (int o = 16; o; o >>= 1) {
        s  += __shfl_down_sync(0xffffffffu, s,  o);
        ss += __shfl_down_sync(0xffffffffu, ss, o);
    }
    int warp = tid >> 5, lane = tid & 31;
    if (lane == 0) { sh[warp] = s; sh[32+warp] = ss; }
    __syncthreads();
    if (warp == 0) {
        s  = (lane < 8) ? sh[lane]    : 0.f;
        ss = (lane < 8) ? sh[32+lane] : 0.f;
#pragma unroll
        for (int o = 4; o; o >>= 1) {
            s  += __shfl_down_sync(0xffffffffu, s,  o);
            ss += __shfl_down_sync(0xffffffffu, ss, o);
        }
        if (lane == 0) {
            float n    = (float)(BATCH) * (float)HW;
            float mean = s / n;
            float var  = ss / n - mean*mean;
            float inv  = rsqrtf(var + 1e-5f);
            float sc   = gamma[c] * inv;
            scale[c] = sc;
            shift[c] = beta[c] - mean * sc;
        }
    }
}

// ---------------- BN1 affine + 2x2 avg pool -> zero-padded plane ----------------
__global__ void __launch_bounds__(256)
pool_bn_kernel()
{
    int idx = blockIdx.x * 256 + threadIdx.x;
    const int total = BATCH*C1*HWP;
    if (idx >= total) return;
    int pw = idx % WP;
    int ph = (idx / WP) % HP;
    int c  = (idx / HWP) % C1;
    int b  = idx / (HWP*C1);
    float v = 0.f;
    if (ph >= 1 && ph <= H2 && pw >= 1 && pw <= W2) {
        int h = ph - 1, w = pw - 1;
        const float* p = g_h1 + (((size_t)b*C1 + c)*H1 + 2*h)*W1 + 2*w;
        float m = 0.25f * (p[0] + p[1] + p[W1] + p[W1+1]);
        v = m * g_scale1[c] + g_shift1[c];
    }
    g_poolpad[idx] = v;
}

// ---------------- BN2 apply -> zero-padded plane ----------------
__global__ void __launch_bounds__(256)
bn2_apply_kernel()
{
    int idx = blockIdx.x * 256 + threadIdx.x;
    const int total = BATCH*C2*HWP;
    if (idx >= total) return;
    int pw = idx % WP;
    int ph = (idx / WP) % HP;
    int c  = (idx / HWP) % C2;
    int b  = idx / (HWP*C2);
    float v = 0.f;
    if (ph >= 1 && ph <= H2 && pw >= 1 && pw <= W2) {
        size_t off = (((size_t)b*C2 + c)*H2 + (ph-1))*W2 + (pw-1);
        v = g_h2[off] * g_scale2[c] + g_shift2[c];
    }
    g_h2pad[idx] = v;
}

// ---------------- conv2 as im2col-GEMM: 128oc x 64px tile, 4x8 reg tile ----------------
__global__ void __launch_bounds__(256)
conv2_gemm_kernel(const float* __restrict__ wT, const float* __restrict__ bias,
                  float* __restrict__ out)
{
    __shared__ __align__(16) float s_x[36*64];    // [icr*9+n][px]
    __shared__ __align__(16) float s_w[36*128];   // [r][oc]

    const int tid = threadIdx.x;
    const int blk = blockIdx.x;          // 784
    const int b   = blk / 196;
    const int hw0 = (blk % 196) * 64;

    const int p  = tid & 63;
    const int hw = hw0 + p;
    const int h  = hw / W2, w = hw % W2; // logical output coords
    const float* inb = g_poolpad + (size_t)b*C1*HWP;

    const int ocg = tid >> 3;  // 0..31
    const int pxg = tid & 7;   // 0..7
    float acc[4][8] = {};

    for (int ic0 = 0; ic0 < C1; ic0 += 4) {
        __syncthreads();
        // gather 4 ic x 9 taps x 64 px from padded input (branch-free)
        for (int rr = (tid >> 6); rr < 36; rr += 4) {
            int icr = rr / 9, n = rr % 9;
            int dh = n / 3, dw = n % 3;
            s_x[rr*64 + p] = inb[((size_t)(ic0+icr)*HP + h + dh)*WP + (w + dw)];
        }
        // weights: contiguous float4 copy
        {
            const float4* src = (const float4*)(wT + (size_t)ic0*9*C2);
            float4* dst = (float4*)s_w;
            for (int e = tid; e < 36*128/4; e += 256) dst[e] = src[e];
        }
        __syncthreads();

#pragma unroll
        for (int r = 0; r < 36; r++) {
            float4 wv = *(const float4*)(s_w + r*128 + ocg*4);
            float4 x0 = *(const float4*)(s_x + r*64 + pxg*8);
            float4 x1 = *(const float4*)(s_x + r*64 + pxg*8 + 4);
            float av[4] = {wv.x, wv.y, wv.z, wv.w};
            float xv[8] = {x0.x, x0.y, x0.z, x0.w, x1.x, x1.y, x1.z, x1.w};
#pragma unroll
            for (int i = 0; i < 4; i++)
#pragma unroll
                for (int j = 0; j < 8; j++)
                    acc[i][j] = fmaf(av[i], xv[j], acc[i][j]);
        }
    }

#pragma unroll
    for (int i = 0; i < 4; i++) {
        int oc = ocg*4 + i;
        float bv = bias[oc];
        float* o = out + ((size_t)b*C2 + oc)*HW2 + hw0 + pxg*8;
        float4 v0 = make_float4(fmaxf(acc[i][0]+bv,0.f), fmaxf(acc[i][1]+bv,0.f),
                                fmaxf(acc[i][2]+bv,0.f), fmaxf(acc[i][3]+bv,0.f));
        float4 v1 = make_float4(fmaxf(acc[i][4]+bv,0.f), fmaxf(acc[i][5]+bv,0.f),
                                fmaxf(acc[i][6]+bv,0.f), fmaxf(acc[i][7]+bv,0.f));
        *(float4*)o       = v0;
        *(float4*)(o + 4) = v1;
    }
}

// ---------------- deformable conv GEMM: 128oc x 64px tile, 4x8 reg tile ----------------
__global__ void __launch_bounds__(256)
deform_gemm_kernel(const float* __restrict__ wT, float* __restrict__ out)
{
    __shared__ int   s_i0[576], s_i1[576], s_i2[576], s_i3[576];  // [n*64+p]
    __shared__ float s_b0[576], s_b1[576], s_b2[576], s_b3[576];
    __shared__ __align__(16) float s_x[36*64];
    __shared__ __align__(16) float s_w[36*128];

    const int tid = threadIdx.x;
    const int blk = blockIdx.x;          // 784
    const int b   = blk / 196;
    const int hw0 = (blk % 196) * 64;

    // Phase 0: bilinear params per (tap, pixel), shared across all 128 channels
    for (int e = tid; e < 576; e += 256) {
        int pp = e & 63, n = e >> 6;
        int hw = hw0 + pp;
        int h = hw / W2, w = hw % W2;
        float ox = g_offs[((size_t)b*COFF + n)     * HW2 + hw];
        float oy = g_offs[((size_t)b*COFF + 9 + n) * HW2 + hw];
        float pX = (float)(h + 1) + (float)(n/3 - 1) + ox;
        float pY = (float)(w + 1) + (float)(n%3 - 1) + oy;
        float fx = floorf(pX), fy = floorf(pY);
        float qltx = fminf(fmaxf(fx,      0.f), (float)(HP-1));
        float qlty = fminf(fmaxf(fy,      0.f), (float)(WP-1));
        float qrbx = fminf(fmaxf(fx+1.f,  0.f), (float)(HP-1));
        float qrby = fminf(fmaxf(fy+1.f,  0.f), (float)(WP-1));
        bool mx = (pX < 1.f) || (pX > (float)(HP-2));
        bool my = (pY < 1.f) || (pY > (float)(WP-2));
        float pxc = fminf(fmaxf(mx ? fx : pX, 0.f), (float)(HP-1));
        float pyc = fminf(fmaxf(my ? fy : pY, 0.f), (float)(WP-1));
        float glt = (1.f + (qltx - pxc)) * (1.f + (qlty - pyc));
        float grb = (1.f - (qrbx - pxc)) * (1.f - (qrby - pyc));
        float glb = (1.f + (qltx - pxc)) * (1.f - (qrby - pyc));
        float grt = (1.f - (qrbx - pxc)) * (1.f + (qlty - pyc));
        int ix0 = (int)qltx, iy0 = (int)qlty;
        int ix1 = (int)qrbx, iy1 = (int)qrby;
        s_i0[e] = ix0*WP + iy0;  s_b0[e] = glt;
        s_i1[e] = ix1*WP + iy1;  s_b1[e] = grb;
        s_i2[e] = ix0*WP + iy1;  s_b2[e] = glb;
        s_i3[e] = ix1*WP + iy0;  s_b3[e] = grt;
    }

    const int p   = tid & 63;
    const int ocg = tid >> 3;
    const int pxg = tid & 7;
    float acc[4][8] = {};
    const float* base = g_h2pad + (size_t)b*C2*HWP;

    for (int ic0 = 0; ic0 < C2; ic0 += 4) {
        __syncthreads();  // also covers phase0 -> first chunk
        // bilinear gather slab: 4 ic x 9 taps x 64 px
        for (int rr = (tid >> 6); rr < 36; rr += 4) {
            int icr = rr / 9, n = rr % 9;
            int q = n*64 + p;
            const float* plane = base + (size_t)(ic0+icr)*HWP;
            float v = s_b0[q] * __ldg(plane + s_i0[q])
                    + s_b1[q] * __ldg(plane + s_i1[q])
                    + s_b2[q] * __ldg(plane + s_i2[q])
                    + s_b3[q] * __ldg(plane + s_i3[q]);
            s_x[rr*64 + p] = v;
        }
        // weights: contiguous float4 copy
        {
            const float4* src = (const float4*)(wT + (size_t)ic0*9*C2);
            float4* dst = (float4*)s_w;
            for (int e = tid; e < 36*128/4; e += 256) dst[e] = src[e];
        }
        __syncthreads();

#pragma unroll
        for (int r = 0; r < 36; r++) {
            float4 wv = *(const float4*)(s_w + r*128 + ocg*4);
            float4 x0 = *(const float4*)(s_x + r*64 + pxg*8);
            float4 x1 = *(const float4*)(s_x + r*64 + pxg*8 + 4);
            float av[4] = {wv.x, wv.y, wv.z, wv.w};
            float xv[8] = {x0.x, x0.y, x0.z, x0.w, x1.x, x1.y, x1.z, x1.w};
#pragma unroll
            for (int i = 0; i < 4; i++)
#pragma unroll
                for (int j = 0; j < 8; j++)
                    acc[i][j] = fmaf(av[i], xv[j], acc[i][j]);
        }
    }

#pragma unroll
    for (int i = 0; i < 4; i++) {
        int oc = ocg*4 + i;
        float* o = out + ((size_t)b*C2 + oc)*HW2 + hw0 + pxg*8;
        *(float4*)o       = make_float4(acc[i][0], acc[i][1], acc[i][2], acc[i][3]);
        *(float4*)(o + 4) = make_float4(acc[i][4], acc[i][5], acc[i][6], acc[i][7]);
    }
}

// ---------------- launch ----------------
extern "C" void kernel_launch(void* const* d_in, const int* in_sizes, int n_in,
                              void* d_out, int out_size)
{
    const float* x       = (const float*)d_in[0];
    const float* conv1_w = (const float*)d_in[1];
    const float* conv1_b = (const float*)d_in[2];
    const float* bn1_g   = (const float*)d_in[3];
    const float* bn1_b   = (const float*)d_in[4];
    const float* conv2_w = (const float*)d_in[5];
    const float* conv2_b = (const float*)d_in[6];
    const float* bn2_g   = (const float*)d_in[7];
    const float* bn2_b   = (const float*)d_in[8];
    const float* off_w   = (const float*)d_in[9];
    const float* off_b   = (const float*)d_in[10];
    const float* conv4_w = (const float*)d_in[11];
    float* out = (float*)d_out;

    float *p_h1, *p_h2, *p_offs, *p_s1, *p_t1, *p_s2, *p_t2, *p_w2T, *p_w4T, *p_h2pad;
    cudaGetSymbolAddress((void**)&p_h1,    g_h1);
    cudaGetSymbolAddress((void**)&p_h2,    g_h2);
    cudaGetSymbolAddress((void**)&p_offs,  g_offs);
    cudaGetSymbolAddress((void**)&p_s1,    g_scale1);
    cudaGetSymbolAddress((void**)&p_t1,    g_shift1);
    cudaGetSymbolAddress((void**)&p_s2,    g_scale2);
    cudaGetSymbolAddress((void**)&p_t2,    g_shift2);
    cudaGetSymbolAddress((void**)&p_w2T,   g_wt2T);
    cudaGetSymbolAddress((void**)&p_w4T,   g_wt4T);
    cudaGetSymbolAddress((void**)&p_h2pad, g_h2pad);

    // 0) weight transposes (tiny)
    transpose_w_kernel<<<(C2*C1*9 + 255)/256, 256>>>(conv2_w, p_w2T, C1, C2);
    transpose_w_kernel<<<(C2*C2*9 + 255)/256, 256>>>(conv4_w, p_w4T, C2, C2);

    // 1) conv1 + bias + relu : 4x3x224x224 -> 4x64x224x224
    {
        dim3 grid(14*14, C1/16, BATCH);
        conv3x3_kernel<3, 16, true><<<grid, 128>>>(x, conv1_w, conv1_b, p_h1,
                                                   3, C1, H1, W1, 14);
    }
    // 2) BN1 stats
    bn_stats_kernel<<<C1, 256>>>(p_h1, bn1_g, bn1_b, p_s1, p_t1, C1, H1*W1);
    // 3) BN1 affine + 2x2 avgpool -> padded 4x64x114x114
    pool_bn_kernel<<<(BATCH*C1*HWP)/256, 256>>>();
    // 4) conv2 (GEMM) + bias + relu : -> 4x128x112x112
    conv2_gemm_kernel<<<BATCH*(HW2/64), 256>>>(p_w2T, conv2_b, p_h2);
    // 5) BN2 stats
    bn_stats_kernel<<<C2, 256>>>(p_h2, bn2_g, bn2_b, p_s2, p_t2, C2, H2*W2);
    // 6) BN2 apply -> padded 4x128x114x114
    bn2_apply_kernel<<<(BATCH*C2*HWP)/256, 256>>>();
    // 7) offsets conv : 128 -> 18 (+bias), reads padded plane
    {
        dim3 grid(7*7, COFF/6, BATCH);
        conv3x3_pad_kernel<16, 6><<<grid, 128>>>(p_h2pad, off_w, off_b, p_offs,
                                                 C2, COFF, H2, W2, 7);
    }
    // 8) deformable conv (GEMM) -> d_out 4x128x112x112
    deform_gemm_kernel<<<BATCH*(HW2/64), 256>>>(p_w4T, out);
}

// round 5
// speedup vs baseline: 1.3134x; 1.3126x over previous
#include <cuda_runtime.h>
#include <math.h>

// ---------------- problem constants ----------------
#define BATCH 4
#define C1    64
#define H1    224
#define W1    224
#define C2    128
#define H2    112
#define W2    112
#define HP    114
#define WP    114
#define HW2   (H2*W2)      // 12544
#define HWP   (HP*WP)      // 12996
#define COFF  18
#define NBLK2 392          // 32-px tiles per image (12544/32)
#define GBLK  (BATCH*NBLK2) // 1568

// smem row strides for the MMA GEMM tiles (bank-conflict free: stride%32==8)
#define XS 40    // s_x rows: 72 x 40
#define WS 136   // s_w rows: 72 x 136

// ---------------- scratch (__device__ globals; zero-initialized, no allocation) ----------------
__device__ float    g_poolpad[BATCH*C1*HWP];   // pooled conv1 (raw, then BN1-affined in place); border stays 0
__device__ float    g_h2[BATCH*C2*HW2];        // relu(conv2+bias) raw
__device__ float    g_h2pad[BATCH*C2*HWP];     // BN2 normalized, zero-padded (border stays 0)
__device__ float    g_offs[BATCH*COFF*HW2];
__device__ unsigned g_w2h[C1*9*C2], g_w2l[C1*9*C2];   // conv2 W^T tf32 hi/lo  [ic*9+n][oc]
__device__ unsigned g_w4h[C2*9*C2], g_w4l[C2*9*C2];   // conv4 W^T tf32 hi/lo
__device__ float    g_p1s[C1*784],  g_p1q[C1*784];    // BN1 per-block partials
__device__ float    g_p2s[C2*GBLK], g_p2q[C2*GBLK];   // BN2 per-block partials
__device__ float    g_scale1[C1], g_shift1[C1];
__device__ float    g_scale2[C2], g_shift2[C2];

// ---------------- tf32 helpers ----------------
__device__ __forceinline__ unsigned f2tf32(float f) {
    unsigned r; asm("cvt.rna.tf32.f32 %0, %1;" : "=r"(r) : "f"(f)); return r;
}
__device__ __forceinline__ void mma_tf32(float& d0, float& d1, float& d2, float& d3,
                                         unsigned a0, unsigned a1, unsigned a2, unsigned a3,
                                         unsigned b0, unsigned b1) {
    asm volatile("mma.sync.aligned.m16n8k8.row.col.f32.tf32.tf32.f32 "
                 "{%0,%1,%2,%3},{%4,%5,%6,%7},{%8,%9},{%0,%1,%2,%3};"
                 : "+f"(d0), "+f"(d1), "+f"(d2), "+f"(d3)
                 : "r"(a0), "r"(a1), "r"(a2), "r"(a3), "r"(b0), "r"(b1));
}

// ---------------- weight transpose + tf32 hi/lo split: w[oc][ic][9] -> [ic*9+n][oc] ----------------
__global__ void __launch_bounds__(256)
split_w_kernel(const float* __restrict__ w, unsigned* __restrict__ wh,
               unsigned* __restrict__ wl, int C_in, int C_out)
{
    int idx = blockIdx.x * 256 + threadIdx.x;
    int total = C_out * C_in * 9;
    if (idx >= total) return;
    int oc = idx % C_out;
    int r  = idx / C_out;
    int ic = r / 9, n = r % 9;
    float v = w[((size_t)oc*C_in + ic)*9 + n];
    unsigned h = f2tf32(v);
    float lo = v - __uint_as_float(h);
    wh[idx] = h;
    wl[idx] = f2tf32(lo);
}

// ---------------- conv1 fused: 3x3 conv + bias + relu + BN1 partial stats + 2x2 pool ----------------
__global__ void __launch_bounds__(128)
conv1_fused_kernel(const float* __restrict__ x, const float* __restrict__ wgt,
                   const float* __restrict__ bias)
{
    __shared__ float s_in[3][18][18];
    __shared__ float s_w[16][3][9];
    __shared__ float s_red[2][16][4];

    const int tileX  = (blockIdx.x % 14) * 16;
    const int tileY  = (blockIdx.x / 14) * 16;
    const int ocBase = blockIdx.y * 16;
    const int b      = blockIdx.z;
    const int tid    = threadIdx.x;
    const int tx     = tid & 15;
    const int ty     = tid >> 4;

    for (int e = tid; e < 3*18*18; e += 128) {
        int ic = e / 324;
        int r  = (e / 18) % 18;
        int c  = e % 18;
        int gy = tileY + r - 1, gx = tileX + c - 1;
        float v = 0.f;
        if (gy >= 0 && gy < H1 && gx >= 0 && gx < W1)
            v = x[(((size_t)b*3 + ic)*H1 + gy)*W1 + gx];
        s_in[ic][r][c] = v;
    }
    for (int e = tid; e < 16*27; e += 128) {
        int oc = e / 27, r = e % 27;
        int ic = r / 9, k = r % 9;
        s_w[oc][ic][k] = wgt[((size_t)(ocBase+oc)*3 + ic)*9 + k];
    }
    __syncthreads();

    float acc0[16], acc1[16];
#pragma unroll
    for (int i = 0; i < 16; i++) { acc0[i] = 0.f; acc1[i] = 0.f; }
    const int y0 = ty * 2;
#pragma unroll
    for (int ic = 0; ic < 3; ic++) {
        float r[4][3];
#pragma unroll
        for (int rr = 0; rr < 4; rr++)
#pragma unroll
            for (int cc = 0; cc < 3; cc++)
                r[rr][cc] = s_in[ic][y0+rr][tx+cc];
#pragma unroll
        for (int oc = 0; oc < 16; oc++) {
            float a0 = acc0[oc], a1 = acc1[oc];
#pragma unroll
            for (int k = 0; k < 9; k++) {
                float wv = s_w[oc][ic][k];
                a0 = fmaf(r[k/3  ][k%3], wv, a0);
                a1 = fmaf(r[k/3+1][k%3], wv, a1);
            }
            acc0[oc] = a0; acc1[oc] = a1;
        }
    }

    const int warp = tid >> 5, lane = tid & 31;
    const int prow = (tileY >> 1) + ty + 1;      // padded pooled coords
    const int pcol = (tileX >> 1) + (tx >> 1) + 1;
    const int blkId = blockIdx.x + 196 * blockIdx.z;   // 0..783

#pragma unroll
    for (int oc = 0; oc < 16; oc++) {
        float bv = bias[ocBase + oc];
        float v0 = fmaxf(acc0[oc] + bv, 0.f);
        float v1 = fmaxf(acc1[oc] + bv, 0.f);
        float pv = v0 + v1;
        float po = pv + __shfl_xor_sync(0xffffffffu, pv, 1);
        if ((tx & 1) == 0)
            g_poolpad[(((size_t)b*C1 + ocBase + oc)*HP + prow)*WP + pcol] = 0.25f * po;
        float s = pv, q = v0*v0 + v1*v1;
#pragma unroll
        for (int o = 16; o; o >>= 1) {
            s += __shfl_down_sync(0xffffffffu, s, o);
            q += __shfl_down_sync(0xffffffffu, q, o);
        }
        if (lane == 0) { s_red[0][oc][warp] = s; s_red[1][oc][warp] = q; }
    }
    __syncthreads();
    if (tid < 16) {
        float S = s_red[0][tid][0] + s_red[0][tid][1] + s_red[0][tid][2] + s_red[0][tid][3];
        float Q = s_red[1][tid][0] + s_red[1][tid][1] + s_red[1][tid][2] + s_red[1][tid][3];
        g_p1s[(size_t)(ocBase + tid)*784 + blkId] = S;
        g_p1q[(size_t)(ocBase + tid)*784 + blkId] = Q;
    }
}

// ---------------- BN finalize: partial sums -> scale/shift ----------------
__global__ void __launch_bounds__(256)
bn_finalize_kernel(const float* __restrict__ ps, const float* __restrict__ pq,
                   const float* __restrict__ gamma, const float* __restrict__ beta,
                   float* __restrict__ scale, float* __restrict__ shift,
                   int nblk, float inv_count)
{
    const int c = blockIdx.x;
    const int tid = threadIdx.x;
    float s = 0.f, q = 0.f;
    for (int i = tid; i < nblk; i += 256) {
        s += ps[(size_t)c*nblk + i];
        q += pq[(size_t)c*nblk + i];
    }
    __shared__ float sh[64];
#pragma unroll
    for (int o = 16; o; o >>= 1) {
        s += __shfl_down_sync(0xffffffffu, s, o);
        q += __shfl_down_sync(0xffffffffu, q, o);
    }
    int warp = tid >> 5, lane = tid & 31;
    if (lane == 0) { sh[warp] = s; sh[32+warp] = q; }
    __syncthreads();
    if (warp == 0) {
        s = (lane < 8) ? sh[lane]    : 0.f;
        q = (lane < 8) ? sh[32+lane] : 0.f;
#pragma unroll
        for (int o = 4; o; o >>= 1) {
            s += __shfl_down_sync(0xffffffffu, s, o);
            q += __shfl_down_sync(0xffffffffu, q, o);
        }
        if (lane == 0) {
            float mean = s * inv_count;
            float var  = q * inv_count - mean*mean;
            float inv  = rsqrtf(var + 1e-5f);
            float sc   = gamma[c] * inv;
            scale[c] = sc;
            shift[c] = beta[c] - mean * sc;
        }
    }
}

// ---------------- BN1 affine applied in place on pooled interior ----------------
__global__ void __launch_bounds__(256)
bn1_apply_kernel()
{
    int idx = blockIdx.x * 256 + threadIdx.x;     // over BATCH*C1*HW2
    int w = idx % W2;
    int h = (idx / W2) % H2;
    int c = (idx / HW2) % C1;
    int b = idx / (HW2*C1);
    size_t p = (((size_t)b*C1 + c)*HP + h + 1)*WP + w + 1;
    g_poolpad[p] = g_poolpad[p] * g_scale1[c] + g_shift1[c];
}

// ---------------- BN2 apply -> zero-padded plane ----------------
__global__ void __launch_bounds__(256)
bn2_apply_kernel()
{
    int idx = blockIdx.x * 256 + threadIdx.x;     // over BATCH*C2*HW2
    int w = idx % W2;
    int h = (idx / W2) % H2;
    int c = (idx / HW2) % C2;
    int b = idx / (HW2*C2);
    size_t p = (((size_t)b*C2 + c)*HP + h + 1)*WP + w + 1;
    g_h2pad[p] = g_h2[idx] * g_scale2[c] + g_shift2[c];
}

// ---------------- conv2 as tf32-3x MMA GEMM: 32px x 128oc, Kc=72 ----------------
// + fused bias/relu + BN2 partial stats
__global__ void __launch_bounds__(256)
conv2_mma_kernel(const float* __restrict__ bias, float* __restrict__ out)
{
    extern __shared__ unsigned smem_u[];
    unsigned* s_xh = smem_u;                 // 72*XS
    unsigned* s_xl = s_xh + 72*XS;
    unsigned* s_wh = s_xl + 72*XS;           // 72*WS
    unsigned* s_wl = s_wh + 72*WS;

    const int tid  = threadIdx.x;
    const int blk  = blockIdx.x;             // 0..1567
    const int b    = blk / NBLK2;
    const int hw0  = (blk % NBLK2) * 32;
    const int lane = tid & 31, wid = tid >> 5;
    const int g    = lane >> 2, t4 = lane & 3;
    const int wm   = wid & 1,  wn = wid >> 1;
    const int px0  = wm * 16;

    const float* inb = g_poolpad + (size_t)b*C1*HWP;
    float acc[4][4] = {};

    for (int ic0 = 0; ic0 < C1; ic0 += 8) {
        __syncthreads();
        // gather: 8 ic x 9 taps x 32 px, tf32 split
        for (int e = tid; e < 2304; e += 256) {
            int r  = e >> 5, px = e & 31;
            int icr = r / 9, n = r - icr*9;
            int hw = hw0 + px;
            int h  = hw / W2, w = hw - h*W2;
            float v = inb[((size_t)(ic0+icr)*HP + h + n/3)*WP + w + n%3];
            unsigned hb = f2tf32(v);
            float lo = v - __uint_as_float(hb);
            s_xh[r*XS + px] = hb;
            s_xl[r*XS + px] = f2tf32(lo);
        }
        // weights: 72 rows x 128 oc, uint4 copies into padded rows
        {
            const uint4* sh4 = (const uint4*)(g_w2h + (size_t)ic0*9*C2);
            const uint4* sl4 = (const uint4*)(g_w2l + (size_t)ic0*9*C2);
            for (int e = tid; e < 2304; e += 256) {
                int kr = e >> 5, c4 = e & 31;
                ((uint4*)(s_wh + kr*WS))[c4] = sh4[e];
                ((uint4*)(s_wl + kr*WS))[c4] = sl4[e];
            }
        }
        __syncthreads();

#pragma unroll
        for (int ks = 0; ks < 9; ks++) {
            const unsigned* xh = s_xh + (ks*8 + t4)*XS + px0 + g;
            const unsigned* xl = s_xl + (ks*8 + t4)*XS + px0 + g;
            unsigned ah0 = xh[0], ah1 = xh[8], ah2 = xh[4*XS], ah3 = xh[4*XS+8];
            unsigned al0 = xl[0], al1 = xl[8], al2 = xl[4*XS], al3 = xl[4*XS+8];
            const unsigned* wh = s_wh + (ks*8 + t4)*WS + wn*32 + g;
            const unsigned* wl = s_wl + (ks*8 + t4)*WS + wn*32 + g;
#pragma unroll
            for (int nt = 0; nt < 4; nt++) {
                unsigned bh0 = wh[nt*8], bh1 = wh[4*WS + nt*8];
                unsigned bl0 = wl[nt*8], bl1 = wl[4*WS + nt*8];
                mma_tf32(acc[nt][0],acc[nt][1],acc[nt][2],acc[nt][3], ah0,ah1,ah2,ah3, bh0,bh1);
                mma_tf32(acc[nt][0],acc[nt][1],acc[nt][2],acc[nt][3], ah0,ah1,ah2,ah3, bl0,bl1);
                mma_tf32(acc[nt][0],acc[nt][1],acc[nt][2],acc[nt][3], al0,al1,al2,al3, bh0,bh1);
            }
        }
    }

    __syncthreads();
    float* s_red = (float*)smem_u;   // [wm][oc][{s,q}] = 512 floats
#pragma unroll
    for (int nt = 0; nt < 4; nt++) {
        int oc0 = wn*32 + nt*8 + 2*t4;
        int oc1 = oc0 + 1;
        float b0v = bias[oc0], b1v = bias[oc1];
        int p0 = hw0 + px0 + g, p1 = p0 + 8;
        float v00 = fmaxf(acc[nt][0] + b0v, 0.f);
        float v01 = fmaxf(acc[nt][1] + b1v, 0.f);
        float v10 = fmaxf(acc[nt][2] + b0v, 0.f);
        float v11 = fmaxf(acc[nt][3] + b1v, 0.f);
        out[((size_t)b*C2 + oc0)*HW2 + p0] = v00;
        out[((size_t)b*C2 + oc1)*HW2 + p0] = v01;
        out[((size_t)b*C2 + oc0)*HW2 + p1] = v10;
        out[((size_t)b*C2 + oc1)*HW2 + p1] = v11;
        float s0 = v00 + v10, q0 = v00*v00 + v10*v10;
        float s1 = v01 + v11, q1 = v01*v01 + v11*v11;
#pragma unroll
        for (int o = 4; o <= 16; o <<= 1) {
            s0 += __shfl_xor_sync(0xffffffffu, s0, o);
            q0 += __shfl_xor_sync(0xffffffffu, q0, o);
            s1 += __shfl_xor_sync(0xffffffffu, s1, o);
            q1 += __shfl_xor_sync(0xffffffffu, q1, o);
        }
        if (g == 0) {
            s_red[(wm*128 + oc0)*2 + 0] = s0;
            s_red[(wm*128 + oc0)*2 + 1] = q0;
            s_red[(wm*128 + oc1)*2 + 0] = s1;
            s_red[(wm*128 + oc1)*2 + 1] = q1;
        }
    }
    __syncthreads();
    if (tid < 128) {
        float S = s_red[tid*2]     + s_red[(128+tid)*2];
        float Q = s_red[tid*2 + 1] + s_red[(128+tid)*2 + 1];
        g_p2s[(size_t)tid*GBLK + blk] = S;
        g_p2q[(size_t)tid*GBLK + blk] = Q;
    }
}

// ---------------- deformable conv as tf32-3x MMA GEMM with bilinear gather ----------------
__global__ void __launch_bounds__(256)
deform_mma_kernel(float* __restrict__ out)
{
    extern __shared__ unsigned smem_u[];
    unsigned* s_xh = smem_u;
    unsigned* s_xl = s_xh + 72*XS;
    unsigned* s_wh = s_xl + 72*XS;
    unsigned* s_wl = s_wh + 72*WS;
    int*      s_i  = (int*)(s_wl + 72*WS);        // [corner*288 + n*32+px]
    float*    s_bw = (float*)(s_i + 4*288);

    const int tid  = threadIdx.x;
    const int blk  = blockIdx.x;
    const int b    = blk / NBLK2;
    const int hw0  = (blk % NBLK2) * 32;
    const int lane = tid & 31, wid = tid >> 5;
    const int g    = lane >> 2, t4 = lane & 3;
    const int wm   = wid & 1,  wn = wid >> 1;
    const int px0  = wm * 16;

    // Phase 0: bilinear params per (tap, pixel)
    for (int e = tid; e < 288; e += 256) {
        int px = e & 31, n = e >> 5;
        int hw = hw0 + px;
        int h = hw / W2, w = hw - h*W2;
        float ox = g_offs[((size_t)b*COFF + n)     * HW2 + hw];
        float oy = g_offs[((size_t)b*COFF + 9 + n) * HW2 + hw];
        float pX = (float)(h + 1) + (float)(n/3 - 1) + ox;
        float pY = (float)(w + 1) + (float)(n%3 - 1) + oy;
        float fx = floorf(pX), fy = floorf(pY);
        float qltx = fminf(fmaxf(fx,     0.f), (float)(HP-1));
        float qlty = fminf(fmaxf(fy,     0.f), (float)(WP-1));
        float qrbx = fminf(fmaxf(fx+1.f, 0.f), (float)(HP-1));
        float qrby = fminf(fmaxf(fy+1.f, 0.f), (float)(WP-1));
        bool mx = (pX < 1.f) || (pX > (float)(HP-2));
        bool my = (pY < 1.f) || (pY > (float)(WP-2));
        float pxc = fminf(fmaxf(mx ? fx : pX, 0.f), (float)(HP-1));
        float pyc = fminf(fmaxf(my ? fy : pY, 0.f), (float)(WP-1));
        float glt = (1.f + (qltx - pxc)) * (1.f + (qlty - pyc));
        float grb = (1.f - (qrbx - pxc)) * (1.f - (qrby - pyc));
        float glb = (1.f + (qltx - pxc)) * (1.f - (qrby - pyc));
        float grt = (1.f - (qrbx - pxc)) * (1.f + (qlty - pyc));
        int ix0 = (int)qltx, iy0 = (int)qlty;
        int ix1 = (int)qrbx, iy1 = (int)qrby;
        s_i[0*288 + e] = ix0*WP + iy0;  s_bw[0*288 + e] = glt;
        s_i[1*288 + e] = ix1*WP + iy1;  s_bw[1*288 + e] = grb;
        s_i[2*288 + e] = ix0*WP + iy1;  s_bw[2*288 + e] = glb;
        s_i[3*288 + e] = ix1*WP + iy0;  s_bw[3*288 + e] = grt;
    }

    const float* base = g_h2pad + (size_t)b*C2*HWP;
    float acc[4][4] = {};

    for (int ic0 = 0; ic0 < C2; ic0 += 8) {
        __syncthreads();   // covers phase0 -> first chunk too
        for (int e = tid; e < 2304; e += 256) {
            int r  = e >> 5, px = e & 31;
            int icr = r / 9, n = r - icr*9;
            int q = n*32 + px;
            const float* plane = base + (size_t)(ic0+icr)*HWP;
            float v = s_bw[q]       * __ldg(plane + s_i[q])
                    + s_bw[288+q]   * __ldg(plane + s_i[288+q])
                    + s_bw[576+q]   * __ldg(plane + s_i[576+q])
                    + s_bw[864+q]   * __ldg(plane + s_i[864+q]);
            unsigned hb = f2tf32(v);
            float lo = v - __uint_as_float(hb);
            s_xh[r*XS + px] = hb;
            s_xl[r*XS + px] = f2tf32(lo);
        }
        {
            const uint4* sh4 = (const uint4*)(g_w4h + (size_t)ic0*9*C2);
            const uint4* sl4 = (const uint4*)(g_w4l + (size_t)ic0*9*C2);
            for (int e = tid; e < 2304; e += 256) {
                int kr = e >> 5, c4 = e & 31;
                ((uint4*)(s_wh + kr*WS))[c4] = sh4[e];
                ((uint4*)(s_wl + kr*WS))[c4] = sl4[e];
            }
        }
        __syncthreads();

#pragma unroll
        for (int ks = 0; ks < 9; ks++) {
            const unsigned* xh = s_xh + (ks*8 + t4)*XS + px0 + g;
            const unsigned* xl = s_xl + (ks*8 + t4)*XS + px0 + g;
            unsigned ah0 = xh[0], ah1 = xh[8], ah2 = xh[4*XS], ah3 = xh[4*XS+8];
            unsigned al0 = xl[0], al1 = xl[8], al2 = xl[4*XS], al3 = xl[4*XS+8];
            const unsigned* wh = s_wh + (ks*8 + t4)*WS + wn*32 + g;
            const unsigned* wl = s_wl + (ks*8 + t4)*WS + wn*32 + g;
#pragma unroll
            for (int nt = 0; nt < 4; nt++) {
                unsigned bh0 = wh[nt*8], bh1 = wh[4*WS + nt*8];
                unsigned bl0 = wl[nt*8], bl1 = wl[4*WS + nt*8];
                mma_tf32(acc[nt][0],acc[nt][1],acc[nt][2],acc[nt][3], ah0,ah1,ah2,ah3, bh0,bh1);
                mma_tf32(acc[nt][0],acc[nt][1],acc[nt][2],acc[nt][3], ah0,ah1,ah2,ah3, bl0,bl1);
                mma_tf32(acc[nt][0],acc[nt][1],acc[nt][2],acc[nt][3], al0,al1,al2,al3, bh0,bh1);
            }
        }
    }

#pragma unroll
    for (int nt = 0; nt < 4; nt++) {
        int oc0 = wn*32 + nt*8 + 2*t4;
        int oc1 = oc0 + 1;
        int p0 = hw0 + px0 + g, p1 = p0 + 8;
        out[((size_t)b*C2 + oc0)*HW2 + p0] = acc[nt][0];
        out[((size_t)b*C2 + oc1)*HW2 + p0] = acc[nt][1];
        out[((size_t)b*C2 + oc0)*HW2 + p1] = acc[nt][2];
        out[((size_t)b*C2 + oc1)*HW2 + p1] = acc[nt][3];
    }
}

// ---------------- offsets conv (fp32, reads padded plane) ----------------
template<int IC_CHUNK, int OC_T>
__global__ void __launch_bounds__(128)
conv3x3_pad_kernel(const float* __restrict__ in, const float* __restrict__ wgt,
                   const float* __restrict__ bias, float* __restrict__ out,
                   int C_in, int C_out, int H, int W, int tilesW)
{
    const int TW = 16, TH = 16;
    const int Hp = H + 2, Wp = W + 2;
    __shared__ float s_in[IC_CHUNK][TH+2][TW+2];
    __shared__ float s_w [OC_T][IC_CHUNK][9];

    const int tileX  = (blockIdx.x % tilesW) * TW;
    const int tileY  = (blockIdx.x / tilesW) * TH;
    const int ocBase = blockIdx.y * OC_T;
    const int b      = blockIdx.z;
    const int tid    = threadIdx.x;
    const int tx     = tid & 15;
    const int ty     = tid >> 4;

    float acc0[OC_T], acc1[OC_T];
#pragma unroll
    for (int i = 0; i < OC_T; i++) { acc0[i] = 0.f; acc1[i] = 0.f; }

    for (int ic0 = 0; ic0 < C_in; ic0 += IC_CHUNK) {
        for (int e = tid; e < IC_CHUNK*(TH+2)*(TW+2); e += 128) {
            int ic = e / ((TH+2)*(TW+2));
            int r  = (e / (TW+2)) % (TH+2);
            int c  = e % (TW+2);
            s_in[ic][r][c] =
                in[(((size_t)b*C_in + ic0+ic)*Hp + tileY + r)*Wp + tileX + c];
        }
        for (int e = tid; e < OC_T*IC_CHUNK*9; e += 128) {
            int oc = e / (IC_CHUNK*9);
            int rem = e % (IC_CHUNK*9);
            int ic = rem / 9, k = rem % 9;
            s_w[oc][ic][k] = wgt[((size_t)(ocBase+oc)*C_in + ic0+ic)*9 + k];
        }
        __syncthreads();

        const int y0 = ty * 2;
#pragma unroll
        for (int ic = 0; ic < IC_CHUNK; ic++) {
            float r[4][3];
#pragma unroll
            for (int rr = 0; rr < 4; rr++)
#pragma unroll
                for (int cc = 0; cc < 3; cc++)
                    r[rr][cc] = s_in[ic][y0+rr][tx+cc];
#pragma unroll
            for (int oc = 0; oc < OC_T; oc++) {
                float a0 = acc0[oc], a1 = acc1[oc];
#pragma unroll
                for (int k = 0; k < 9; k++) {
                    float wv = s_w[oc][ic][k];
                    a0 = fmaf(r[k/3  ][k%3], wv, a0);
                    a1 = fmaf(r[k/3+1][k%3], wv, a1);
                }
                acc0[oc] = a0; acc1[oc] = a1;
            }
        }
        __syncthreads();
    }

    const int gy0 = tileY + ty*2;
    const int gx  = tileX + tx;
#pragma unroll
    for (int oc = 0; oc < OC_T; oc++) {
        float bv = bias[ocBase+oc];
        size_t base = (((size_t)b*C_out + ocBase+oc)*H + gy0)*W + gx;
        out[base]     = acc0[oc] + bv;
        out[base + W] = acc1[oc] + bv;
    }
}

// ---------------- launch ----------------
extern "C" void kernel_launch(void* const* d_in, const int* in_sizes, int n_in,
                              void* d_out, int out_size)
{
    const float* x       = (const float*)d_in[0];
    const float* conv1_w = (const float*)d_in[1];
    const float* conv1_b = (const float*)d_in[2];
    const float* bn1_g   = (const float*)d_in[3];
    const float* bn1_b   = (const float*)d_in[4];
    const float* conv2_w = (const float*)d_in[5];
    const float* conv2_b = (const float*)d_in[6];
    const float* bn2_g   = (const float*)d_in[7];
    const float* bn2_b   = (const float*)d_in[8];
    const float* off_w   = (const float*)d_in[9];
    const float* off_b   = (const float*)d_in[10];
    const float* conv4_w = (const float*)d_in[11];
    float* out = (float*)d_out;

    float *p_h2, *p_offs, *p_s1, *p_t1, *p_s2, *p_t2, *p_h2pad;
    float *p_p1s, *p_p1q, *p_p2s, *p_p2q;
    unsigned *p_w2h, *p_w2l, *p_w4h, *p_w4l;
    cudaGetSymbolAddress((void**)&p_h2,    g_h2);
    cudaGetSymbolAddress((void**)&p_offs,  g_offs);
    cudaGetSymbolAddress((void**)&p_s1,    g_scale1);
    cudaGetSymbolAddress((void**)&p_t1,    g_shift1);
    cudaGetSymbolAddress((void**)&p_s2,    g_scale2);
    cudaGetSymbolAddress((void**)&p_t2,    g_shift2);
    cudaGetSymbolAddress((void**)&p_h2pad, g_h2pad);
    cudaGetSymbolAddress((void**)&p_p1s,   g_p1s);
    cudaGetSymbolAddress((void**)&p_p1q,   g_p1q);
    cudaGetSymbolAddress((void**)&p_p2s,   g_p2s);
    cudaGetSymbolAddress((void**)&p_p2q,   g_p2q);
    cudaGetSymbolAddress((void**)&p_w2h,   g_w2h);
    cudaGetSymbolAddress((void**)&p_w2l,   g_w2l);
    cudaGetSymbolAddress((void**)&p_w4h,   g_w4h);
    cudaGetSymbolAddress((void**)&p_w4l,   g_w4l);

    const int SMEM_CONV2  = (2*72*XS + 2*72*WS) * 4;            // 101376 B
    const int SMEM_DEFORM = SMEM_CONV2 + (4*288*2) * 4;         // 110592 B
    cudaFuncSetAttribute(conv2_mma_kernel,
                         cudaFuncAttributeMaxDynamicSharedMemorySize, SMEM_CONV2);
    cudaFuncSetAttribute(deform_mma_kernel,
                         cudaFuncAttributeMaxDynamicSharedMemorySize, SMEM_DEFORM);

    // 0) weight transposes + tf32 hi/lo splits
    split_w_kernel<<<(C2*C1*9 + 255)/256, 256>>>(conv2_w, p_w2h, p_w2l, C1, C2);
    split_w_kernel<<<(C2*C2*9 + 255)/256, 256>>>(conv4_w, p_w4h, p_w4l, C2, C2);

    // 1) conv1 + bias + relu + BN1 partials + 2x2 pool -> padded pooled (raw)
    {
        dim3 grid(196, 4, BATCH);
        conv1_fused_kernel<<<grid, 128>>>(x, conv1_w, conv1_b);
    }
    // 2) BN1 finalize + apply in place
    bn_finalize_kernel<<<C1, 256>>>(p_p1s, p_p1q, bn1_g, bn1_b, p_s1, p_t1,
                                    784, 1.0f/(float)(BATCH*H1*W1));
    bn1_apply_kernel<<<(BATCH*C1*HW2)/256, 256>>>();

    // 3) conv2 (tf32-3x MMA) + bias + relu + BN2 partials
    conv2_mma_kernel<<<GBLK, 256, SMEM_CONV2>>>(conv2_b, p_h2);

    // 4) BN2 finalize + apply into padded plane
    bn_finalize_kernel<<<C2, 256>>>(p_p2s, p_p2q, bn2_g, bn2_b, p_s2, p_t2,
                                    GBLK, 1.0f/(float)(BATCH*HW2));
    bn2_apply_kernel<<<(BATCH*C2*HW2)/256, 256>>>();

    // 5) offsets conv : 128 -> 18 (+bias)
    {
        dim3 grid(7*7, COFF/6, BATCH);
        conv3x3_pad_kernel<16, 6><<<grid, 128>>>(p_h2pad, off_w, off_b, p_offs,
                                                 C2, COFF, H2, W2, 7);
    }
    // 6) deformable conv (tf32-3x MMA) -> d_out
    deform_mma_kernel<<<GBLK, 256, SMEM_DEFORM>>>(out);
}

// round 6
// speedup vs baseline: 1.4699x; 1.1192x over previous
#include <cuda_runtime.h>
#include <math.h>

// ---------------- problem constants ----------------
#define BATCH 4
#define C1    64
#define H1    224
#define W1    224
#define C2    128
#define H2    112
#define W2    112
#define HP    114
#define WP    114
#define HW2   (H2*W2)      // 12544
#define HWP   (HP*WP)      // 12996
#define COFF  18
#define NBLK2 392          // 32-px tiles per image
#define GBLK  (BATCH*NBLK2) // 1568
#define NOFF  98           // 128-px tiles per image (offsets kernel)

// smem strides (bank-conflict free: stride%32==8)
#define XS  40   // activations rows (32 px + pad)
#define WS  136  // weight rows for 128 oc
#define XSO 136  // activations rows for offsets kernel (128 px + pad)
#define WSO 40   // weight rows for 32 oc

// ---------------- scratch (__device__ globals; zero-init, no allocation) ----------------
__device__ float    g_poolpad[BATCH*C1*HWP];   // raw pooled conv1+relu, zero border (never written)
__device__ float    g_h2pad[BATCH*C2*HWP];     // raw relu(conv2+bias), zero border (never written)
__device__ float    g_offs[BATCH*COFF*HW2];
__device__ unsigned g_w2h[C1*9*C2],  g_w2l[C1*9*C2];    // conv2 W^T tf32 hi/lo  [ic*9+n][oc]
__device__ unsigned g_w4h[C2*9*C2],  g_w4l[C2*9*C2];    // conv4 W^T tf32 hi/lo
__device__ unsigned g_wOh[C2*9*32],  g_wOl[C2*9*32];    // offsets W^T padded to 32 oc
__device__ float    g_p1s[C1*784],  g_p1q[C1*784];      // BN1 per-block partials
__device__ float    g_p2s[C2*GBLK], g_p2q[C2*GBLK];     // BN2 per-block partials
__device__ float    g_scale1[C1], g_shift1[C1];
__device__ float    g_scale2[C2], g_shift2[C2];

// ---------------- helpers ----------------
__device__ __forceinline__ unsigned f2tf32(float f) {
    unsigned r; asm("cvt.rna.tf32.f32 %0, %1;" : "=r"(r) : "f"(f)); return r;
}
__device__ __forceinline__ void mma_tf32(float& d0, float& d1, float& d2, float& d3,
                                         unsigned a0, unsigned a1, unsigned a2, unsigned a3,
                                         unsigned b0, unsigned b1) {
    asm volatile("mma.sync.aligned.m16n8k8.row.col.f32.tf32.tf32.f32 "
                 "{%0,%1,%2,%3},{%4,%5,%6,%7},{%8,%9},{%0,%1,%2,%3};"
                 : "+f"(d0), "+f"(d1), "+f"(d2), "+f"(d3)
                 : "r"(a0), "r"(a1), "r"(a2), "r"(a3), "r"(b0), "r"(b1));
}
__device__ __forceinline__ void cp16(void* dst, const void* src) {
    unsigned d = (unsigned)__cvta_generic_to_shared(dst);
    asm volatile("cp.async.cg.shared.global [%0], [%1], 16;" :: "r"(d), "l"(src));
}
__device__ __forceinline__ void cp_commit_wait() {
    asm volatile("cp.async.commit_group;");
    asm volatile("cp.async.wait_group 0;" ::: "memory");
}

// ---------------- weight transpose + tf32 hi/lo split ----------------
__global__ void __launch_bounds__(256)
split_w_kernel(const float* __restrict__ w, unsigned* __restrict__ wh,
               unsigned* __restrict__ wl, int C_in, int C_out)
{
    int idx = blockIdx.x * 256 + threadIdx.x;
    int total = C_out * C_in * 9;
    if (idx >= total) return;
    int oc = idx % C_out;
    int r  = idx / C_out;
    int ic = r / 9, n = r % 9;
    float v = w[((size_t)oc*C_in + ic)*9 + n];
    unsigned h = f2tf32(v);
    wh[idx] = h;
    wl[idx] = f2tf32(v - __uint_as_float(h));
}

// offsets weights: [oc<18][ic][9] -> [ic*9+n][32] (zero-padded oc)
__global__ void __launch_bounds__(256)
split_w_pad_kernel(const float* __restrict__ w, unsigned* __restrict__ wh,
                   unsigned* __restrict__ wl)
{
    int idx = blockIdx.x * 256 + threadIdx.x;
    int total = C2 * 9 * 32;
    if (idx >= total) return;
    int oc = idx % 32;
    int r  = idx / 32;
    int ic = r / 9, n = r % 9;
    float v = (oc < COFF) ? w[((size_t)oc*C2 + ic)*9 + n] : 0.f;
    unsigned h = f2tf32(v);
    wh[idx] = h;
    wl[idx] = f2tf32(v - __uint_as_float(h));
}

// ---------------- conv1 fused: 3x3 conv + bias + relu + BN1 partials + 2x2 pool ----------------
__global__ void __launch_bounds__(128)
conv1_fused_kernel(const float* __restrict__ x, const float* __restrict__ wgt,
                   const float* __restrict__ bias)
{
    __shared__ float s_in[3][18][18];
    __shared__ float s_w[16][3][9];
    __shared__ float s_red[2][16][4];

    const int tileX  = (blockIdx.x % 14) * 16;
    const int tileY  = (blockIdx.x / 14) * 16;
    const int ocBase = blockIdx.y * 16;
    const int b      = blockIdx.z;
    const int tid    = threadIdx.x;
    const int tx     = tid & 15;
    const int ty     = tid >> 4;

    for (int e = tid; e < 3*18*18; e += 128) {
        int ic = e / 324;
        int r  = (e / 18) % 18;
        int c  = e % 18;
        int gy = tileY + r - 1, gx = tileX + c - 1;
        float v = 0.f;
        if (gy >= 0 && gy < H1 && gx >= 0 && gx < W1)
            v = x[(((size_t)b*3 + ic)*H1 + gy)*W1 + gx];
        s_in[ic][r][c] = v;
    }
    for (int e = tid; e < 16*27; e += 128) {
        int oc = e / 27, r = e % 27;
        int ic = r / 9, k = r % 9;
        s_w[oc][ic][k] = wgt[((size_t)(ocBase+oc)*3 + ic)*9 + k];
    }
    __syncthreads();

    float acc0[16], acc1[16];
#pragma unroll
    for (int i = 0; i < 16; i++) { acc0[i] = 0.f; acc1[i] = 0.f; }
    const int y0 = ty * 2;
#pragma unroll
    for (int ic = 0; ic < 3; ic++) {
        float r[4][3];
#pragma unroll
        for (int rr = 0; rr < 4; rr++)
#pragma unroll
            for (int cc = 0; cc < 3; cc++)
                r[rr][cc] = s_in[ic][y0+rr][tx+cc];
#pragma unroll
        for (int oc = 0; oc < 16; oc++) {
            float a0 = acc0[oc], a1 = acc1[oc];
#pragma unroll
            for (int k = 0; k < 9; k++) {
                float wv = s_w[oc][ic][k];
                a0 = fmaf(r[k/3  ][k%3], wv, a0);
                a1 = fmaf(r[k/3+1][k%3], wv, a1);
            }
            acc0[oc] = a0; acc1[oc] = a1;
        }
    }

    const int warp = tid >> 5, lane = tid & 31;
    const int prow = (tileY >> 1) + ty + 1;
    const int pcol = (tileX >> 1) + (tx >> 1) + 1;
    const int blkId = blockIdx.x + 196 * blockIdx.z;

#pragma unroll
    for (int oc = 0; oc < 16; oc++) {
        float bv = bias[ocBase + oc];
        float v0 = fmaxf(acc0[oc] + bv, 0.f);
        float v1 = fmaxf(acc1[oc] + bv, 0.f);
        float pv = v0 + v1;
        float po = pv + __shfl_xor_sync(0xffffffffu, pv, 1);
        if ((tx & 1) == 0)
            g_poolpad[(((size_t)b*C1 + ocBase + oc)*HP + prow)*WP + pcol] = 0.25f * po;
        float s = pv, q = v0*v0 + v1*v1;
#pragma unroll
        for (int o = 16; o; o >>= 1) {
            s += __shfl_down_sync(0xffffffffu, s, o);
            q += __shfl_down_sync(0xffffffffu, q, o);
        }
        if (lane == 0) { s_red[0][oc][warp] = s; s_red[1][oc][warp] = q; }
    }
    __syncthreads();
    if (tid < 16) {
        float S = s_red[0][tid][0] + s_red[0][tid][1] + s_red[0][tid][2] + s_red[0][tid][3];
        float Q = s_red[1][tid][0] + s_red[1][tid][1] + s_red[1][tid][2] + s_red[1][tid][3];
        g_p1s[(size_t)(ocBase + tid)*784 + blkId] = S;
        g_p1q[(size_t)(ocBase + tid)*784 + blkId] = Q;
    }
}

// ---------------- BN finalize: partials -> scale/shift ----------------
__global__ void __launch_bounds__(256)
bn_finalize_kernel(const float* __restrict__ ps, const float* __restrict__ pq,
                   const float* __restrict__ gamma, const float* __restrict__ beta,
                   float* __restrict__ scale, float* __restrict__ shift,
                   int nblk, float inv_count)
{
    const int c = blockIdx.x;
    const int tid = threadIdx.x;
    float s = 0.f, q = 0.f;
    for (int i = tid; i < nblk; i += 256) {
        s += ps[(size_t)c*nblk + i];
        q += pq[(size_t)c*nblk + i];
    }
    __shared__ float sh[64];
#pragma unroll
    for (int o = 16; o; o >>= 1) {
        s += __shfl_down_sync(0xffffffffu, s, o);
        q += __shfl_down_sync(0xffffffffu, q, o);
    }
    int warp = tid >> 5, lane = tid & 31;
    if (lane == 0) { sh[warp] = s; sh[32+warp] = q; }
    __syncthreads();
    if (warp == 0) {
        s = (lane < 8) ? sh[lane]    : 0.f;
        q = (lane < 8) ? sh[32+lane] : 0.f;
#pragma unroll
        for (int o = 4; o; o >>= 1) {
            s += __shfl_down_sync(0xffffffffu, s, o);
            q += __shfl_down_sync(0xffffffffu, q, o);
        }
        if (lane == 0) {
            float mean = s * inv_count;
            float var  = q * inv_count - mean*mean;
            float inv  = rsqrtf(var + 1e-5f);
            float sc   = gamma[c] * inv;
            scale[c] = sc;
            shift[c] = beta[c] - mean * sc;
        }
    }
}

// ---------------- conv2: tf32-2x MMA GEMM, BN1 folded into gather ----------------
// out: raw relu(conv2+bias) into padded plane interior; BN2 partials to global
__global__ void __launch_bounds__(256)
conv2_mma_kernel(const float* __restrict__ bias, float* __restrict__ outpad)
{
    extern __shared__ unsigned smem_u[];
    unsigned* s_x  = smem_u;                  // 72*XS
    unsigned* s_wh = s_x  + 72*XS;            // 72*WS
    unsigned* s_wl = s_wh + 72*WS;
    float*    s_s  = (float*)(s_wl + 72*WS);  // 64
    float*    s_t  = s_s + C1;                // 64

    const int tid  = threadIdx.x;
    const int blk  = blockIdx.x;
    const int b    = blk / NBLK2;
    const int hw0  = (blk % NBLK2) * 32;
    const int lane = tid & 31, wid = tid >> 5;
    const int g    = lane >> 2, t4 = lane & 3;
    const int wm   = wid & 1,  wn = wid >> 1;
    const int px0  = wm * 16;

    if (tid < C1)      s_s[tid] = g_scale1[tid];
    else if (tid < 2*C1) s_t[tid - C1] = g_shift1[tid - C1];

    const float* inb = g_poolpad + (size_t)b*C1*HWP;
    float acc[4][4] = {};

    for (int ic0 = 0; ic0 < C1; ic0 += 8) {
        __syncthreads();
        // weights via cp.async (fly under the gather)
        {
            const uint4* sh4 = (const uint4*)(g_w2h + (size_t)ic0*9*C2);
            const uint4* sl4 = (const uint4*)(g_w2l + (size_t)ic0*9*C2);
            for (int e = tid; e < 2304; e += 256) {
                int kr = e >> 5, c4 = e & 31;
                cp16(s_wh + kr*WS + c4*4, sh4 + e);
                cp16(s_wl + kr*WS + c4*4, sl4 + e);
            }
        }
        // gather with BN1 affine folded (border raw = 0; shift masked by interior)
        for (int e = tid; e < 2304; e += 256) {
            int r  = e >> 5, px = e & 31;
            int icr = r / 9, n = r - icr*9;
            int hw = hw0 + px;
            int h  = hw / W2, w = hw - h*W2;
            int hh = h + n/3, ww = w + n%3;
            float raw = inb[(size_t)(ic0+icr)*HWP + hh*WP + ww];
            float m = ((unsigned)(hh-1) < 112u && (unsigned)(ww-1) < 112u) ? 1.f : 0.f;
            float v = raw * s_s[ic0+icr] + m * s_t[ic0+icr];
            s_x[r*XS + px] = f2tf32(v);
        }
        cp_commit_wait();
        __syncthreads();

#pragma unroll
        for (int ks = 0; ks < 9; ks++) {
            const unsigned* xp = s_x + (ks*8 + t4)*XS + px0 + g;
            unsigned a0 = xp[0], a1 = xp[8], a2 = xp[4*XS], a3 = xp[4*XS+8];
            const unsigned* wh = s_wh + (ks*8 + t4)*WS + wn*32 + g;
            const unsigned* wl = s_wl + (ks*8 + t4)*WS + wn*32 + g;
#pragma unroll
            for (int nt = 0; nt < 4; nt++) {
                unsigned bh0 = wh[nt*8], bh1 = wh[4*WS + nt*8];
                unsigned bl0 = wl[nt*8], bl1 = wl[4*WS + nt*8];
                mma_tf32(acc[nt][0],acc[nt][1],acc[nt][2],acc[nt][3], a0,a1,a2,a3, bh0,bh1);
                mma_tf32(acc[nt][0],acc[nt][1],acc[nt][2],acc[nt][3], a0,a1,a2,a3, bl0,bl1);
            }
        }
    }

    __syncthreads();
    float* s_red = (float*)smem_u;
    const int p0 = hw0 + px0 + g, p1 = p0 + 8;
    const int h0 = p0 / W2, w0 = p0 - h0*W2;
    const int h1 = p1 / W2, w1 = p1 - h1*W2;
#pragma unroll
    for (int nt = 0; nt < 4; nt++) {
        int oc0 = wn*32 + nt*8 + 2*t4;
        int oc1 = oc0 + 1;
        float b0v = bias[oc0], b1v = bias[oc1];
        float v00 = fmaxf(acc[nt][0] + b0v, 0.f);
        float v01 = fmaxf(acc[nt][1] + b1v, 0.f);
        float v10 = fmaxf(acc[nt][2] + b0v, 0.f);
        float v11 = fmaxf(acc[nt][3] + b1v, 0.f);
        outpad[(((size_t)b*C2 + oc0)*HP + h0+1)*WP + w0+1] = v00;
        outpad[(((size_t)b*C2 + oc1)*HP + h0+1)*WP + w0+1] = v01;
        outpad[(((size_t)b*C2 + oc0)*HP + h1+1)*WP + w1+1] = v10;
        outpad[(((size_t)b*C2 + oc1)*HP + h1+1)*WP + w1+1] = v11;
        float s0 = v00 + v10, q0 = v00*v00 + v10*v10;
        float s1 = v01 + v11, q1 = v01*v01 + v11*v11;
#pragma unroll
        for (int o = 4; o <= 16; o <<= 1) {
            s0 += __shfl_xor_sync(0xffffffffu, s0, o);
            q0 += __shfl_xor_sync(0xffffffffu, q0, o);
            s1 += __shfl_xor_sync(0xffffffffu, s1, o);
            q1 += __shfl_xor_sync(0xffffffffu, q1, o);
        }
        if (g == 0) {
            s_red[(wm*128 + oc0)*2 + 0] = s0;
            s_red[(wm*128 + oc0)*2 + 1] = q0;
            s_red[(wm*128 + oc1)*2 + 0] = s1;
            s_red[(wm*128 + oc1)*2 + 1] = q1;
        }
    }
    __syncthreads();
    if (tid < 128) {
        float S = s_red[tid*2]     + s_red[(128+tid)*2];
        float Q = s_red[tid*2 + 1] + s_red[(128+tid)*2 + 1];
        g_p2s[(size_t)tid*GBLK + blk] = S;
        g_p2q[(size_t)tid*GBLK + blk] = Q;
    }
}

// ---------------- offsets conv: tf32-2x MMA, 128px x 32oc(pad of 18), BN2 folded ----------------
__global__ void __launch_bounds__(256)
offs_mma_kernel(const float* __restrict__ bias)
{
    extern __shared__ unsigned smem_u[];
    unsigned* s_x  = smem_u;                   // 72*XSO
    unsigned* s_wh = s_x  + 72*XSO;            // 72*WSO
    unsigned* s_wl = s_wh + 72*WSO;
    float*    s_s  = (float*)(s_wl + 72*WSO);  // 128
    float*    s_t  = s_s + C2;

    const int tid  = threadIdx.x;
    const int blk  = blockIdx.x;
    const int b    = blk / NOFF;
    const int hw0  = (blk % NOFF) * 128;
    const int lane = tid & 31, wid = tid >> 5;
    const int g    = lane >> 2, t4 = lane & 3;
    const int px0  = wid * 16;

    if (tid < C2) { s_s[tid] = g_scale2[tid]; s_t[tid] = g_shift2[tid]; }

    const float* inb = g_h2pad + (size_t)b*C2*HWP;
    float acc[4][4] = {};

    for (int ic0 = 0; ic0 < C2; ic0 += 8) {
        __syncthreads();
        {
            const uint4* sh4 = (const uint4*)(g_wOh + (size_t)ic0*9*32);
            const uint4* sl4 = (const uint4*)(g_wOl + (size_t)ic0*9*32);
            for (int e = tid; e < 576; e += 256) {
                int kr = e >> 3, c4 = e & 7;
                cp16(s_wh + kr*WSO + c4*4, sh4 + e);
                cp16(s_wl + kr*WSO + c4*4, sl4 + e);
            }
        }
        for (int e = tid; e < 9216; e += 256) {
            int r  = e >> 7, px = e & 127;
            int icr = r / 9, n = r - icr*9;
            int hw = hw0 + px;
            int h  = hw / W2, w = hw - h*W2;
            int hh = h + n/3, ww = w + n%3;
            float raw = inb[(size_t)(ic0+icr)*HWP + hh*WP + ww];
            float m = ((unsigned)(hh-1) < 112u && (unsigned)(ww-1) < 112u) ? 1.f : 0.f;
            float v = raw * s_s[ic0+icr] + m * s_t[ic0+icr];
            s_x[r*XSO + px] = f2tf32(v);
        }
        cp_commit_wait();
        __syncthreads();

#pragma unroll
        for (int ks = 0; ks < 9; ks++) {
            const unsigned* xp = s_x + (ks*8 + t4)*XSO + px0 + g;
            unsigned a0 = xp[0], a1 = xp[8], a2 = xp[4*XSO], a3 = xp[4*XSO+8];
            const unsigned* wh = s_wh + (ks*8 + t4)*WSO + g;
            const unsigned* wl = s_wl + (ks*8 + t4)*WSO + g;
#pragma unroll
            for (int nt = 0; nt < 4; nt++) {
                unsigned bh0 = wh[nt*8], bh1 = wh[4*WSO + nt*8];
                unsigned bl0 = wl[nt*8], bl1 = wl[4*WSO + nt*8];
                mma_tf32(acc[nt][0],acc[nt][1],acc[nt][2],acc[nt][3], a0,a1,a2,a3, bh0,bh1);
                mma_tf32(acc[nt][0],acc[nt][1],acc[nt][2],acc[nt][3], a0,a1,a2,a3, bl0,bl1);
            }
        }
    }

    const int p0 = hw0 + px0 + g, p1 = p0 + 8;
#pragma unroll
    for (int nt = 0; nt < 4; nt++) {
        int oc0 = nt*8 + 2*t4;
        int oc1 = oc0 + 1;
        if (oc0 < COFF) {
            float bv = bias[oc0];
            g_offs[((size_t)b*COFF + oc0)*HW2 + p0] = acc[nt][0] + bv;
            g_offs[((size_t)b*COFF + oc0)*HW2 + p1] = acc[nt][2] + bv;
        }
        if (oc1 < COFF) {
            float bv = bias[oc1];
            g_offs[((size_t)b*COFF + oc1)*HW2 + p0] = acc[nt][1] + bv;
            g_offs[((size_t)b*COFF + oc1)*HW2 + p1] = acc[nt][3] + bv;
        }
    }
}

// ---------------- deformable conv: tf32-2x MMA, bilinear gather with BN2 folded ----------------
__global__ void __launch_bounds__(256)
deform_mma_kernel(float* __restrict__ out)
{
    extern __shared__ unsigned smem_u[];
    unsigned* s_x  = smem_u;                    // 72*XS
    unsigned* s_wh = s_x  + 72*XS;              // 72*WS
    unsigned* s_wl = s_wh + 72*WS;
    int*      s_i  = (int*)(s_wl + 72*WS);      // 4*288
    float*    s_bw = (float*)(s_i + 4*288);     // 4*288
    float*    s_ts = s_bw + 4*288;              // 288 (shift weight sum)
    float*    s_s  = s_ts + 288;                // 128
    float*    s_t  = s_s + C2;                  // 128

    const int tid  = threadIdx.x;
    const int blk  = blockIdx.x;
    const int b    = blk / NBLK2;
    const int hw0  = (blk % NBLK2) * 32;
    const int lane = tid & 31, wid = tid >> 5;
    const int g    = lane >> 2, t4 = lane & 3;
    const int wm   = wid & 1,  wn = wid >> 1;
    const int px0  = wm * 16;

    if (tid < C2) { s_s[tid] = g_scale2[tid]; s_t[tid] = g_shift2[tid]; }

    // Phase 0: bilinear params + interior-masked shift weight sum
    for (int e = tid; e < 288; e += 256) {
        int px = e & 31, n = e >> 5;
        int hw = hw0 + px;
        int h = hw / W2, w = hw - h*W2;
        float ox = g_offs[((size_t)b*COFF + n)     * HW2 + hw];
        float oy = g_offs[((size_t)b*COFF + 9 + n) * HW2 + hw];
        float pX = (float)(h + 1) + (float)(n/3 - 1) + ox;
        float pY = (float)(w + 1) + (float)(n%3 - 1) + oy;
        float fx = floorf(pX), fy = floorf(pY);
        float qltx = fminf(fmaxf(fx,     0.f), (float)(HP-1));
        float qlty = fminf(fmaxf(fy,     0.f), (float)(WP-1));
        float qrbx = fminf(fmaxf(fx+1.f, 0.f), (float)(HP-1));
        float qrby = fminf(fmaxf(fy+1.f, 0.f), (float)(WP-1));
        bool mx = (pX < 1.f) || (pX > (float)(HP-2));
        bool my = (pY < 1.f) || (pY > (float)(WP-2));
        float pxc = fminf(fmaxf(mx ? fx : pX, 0.f), (float)(HP-1));
        float pyc = fminf(fmaxf(my ? fy : pY, 0.f), (float)(WP-1));
        float glt = (1.f + (qltx - pxc)) * (1.f + (qlty - pyc));
        float grb = (1.f - (qrbx - pxc)) * (1.f - (qrby - pyc));
        float glb = (1.f + (qltx - pxc)) * (1.f - (qrby - pyc));
        float grt = (1.f - (qrbx - pxc)) * (1.f + (qlty - pyc));
        int ix0 = (int)qltx, iy0 = (int)qlty;
        int ix1 = (int)qrbx, iy1 = (int)qrby;
        s_i[0*288 + e] = ix0*WP + iy0;  s_bw[0*288 + e] = glt;
        s_i[1*288 + e] = ix1*WP + iy1;  s_bw[1*288 + e] = grb;
        s_i[2*288 + e] = ix0*WP + iy1;  s_bw[2*288 + e] = glb;
        s_i[3*288 + e] = ix1*WP + iy0;  s_bw[3*288 + e] = grt;
        // interior indicator per corner (padded plane interior = [1,112]^2)
        float m0 = ((unsigned)(ix0-1) < 112u && (unsigned)(iy0-1) < 112u) ? 1.f : 0.f;
        float m1 = ((unsigned)(ix1-1) < 112u && (unsigned)(iy1-1) < 112u) ? 1.f : 0.f;
        float m2 = ((unsigned)(ix0-1) < 112u && (unsigned)(iy1-1) < 112u) ? 1.f : 0.f;
        float m3 = ((unsigned)(ix1-1) < 112u && (unsigned)(iy0-1) < 112u) ? 1.f : 0.f;
        s_ts[e] = glt*m0 + grb*m1 + glb*m2 + grt*m3;
    }

    const float* base = g_h2pad + (size_t)b*C2*HWP;
    float acc[4][4] = {};

    for (int ic0 = 0; ic0 < C2; ic0 += 8) {
        __syncthreads();
        {
            const uint4* sh4 = (const uint4*)(g_w4h + (size_t)ic0*9*C2);
            const uint4* sl4 = (const uint4*)(g_w4l + (size_t)ic0*9*C2);
            for (int e = tid; e < 2304; e += 256) {
                int kr = e >> 5, c4 = e & 31;
                cp16(s_wh + kr*WS + c4*4, sh4 + e);
                cp16(s_wl + kr*WS + c4*4, sl4 + e);
            }
        }
        for (int e = tid; e < 2304; e += 256) {
            int r  = e >> 5, px = e & 31;
            int icr = r / 9, n = r - icr*9;
            int q = n*32 + px;
            const float* plane = base + (size_t)(ic0+icr)*HWP;
            float rawsum = s_bw[q]     * __ldg(plane + s_i[q])
                         + s_bw[288+q] * __ldg(plane + s_i[288+q])
                         + s_bw[576+q] * __ldg(plane + s_i[576+q])
                         + s_bw[864+q] * __ldg(plane + s_i[864+q]);
            float v = rawsum * s_s[ic0+icr] + s_ts[q] * s_t[ic0+icr];
            s_x[r*XS + px] = f2tf32(v);
        }
        cp_commit_wait();
        __syncthreads();

#pragma unroll
        for (int ks = 0; ks < 9; ks++) {
            const unsigned* xp = s_x + (ks*8 + t4)*XS + px0 + g;
            unsigned a0 = xp[0], a1 = xp[8], a2 = xp[4*XS], a3 = xp[4*XS+8];
            const unsigned* wh = s_wh + (ks*8 + t4)*WS + wn*32 + g;
            const unsigned* wl = s_wl + (ks*8 + t4)*WS + wn*32 + g;
#pragma unroll
            for (int nt = 0; nt < 4; nt++) {
                unsigned bh0 = wh[nt*8], bh1 = wh[4*WS + nt*8];
                unsigned bl0 = wl[nt*8], bl1 = wl[4*WS + nt*8];
                mma_tf32(acc[nt][0],acc[nt][1],acc[nt][2],acc[nt][3], a0,a1,a2,a3, bh0,bh1);
                mma_tf32(acc[nt][0],acc[nt][1],acc[nt][2],acc[nt][3], a0,a1,a2,a3, bl0,bl1);
            }
        }
    }

    const int p0 = hw0 + px0 + g, p1 = p0 + 8;
#pragma unroll
    for (int nt = 0; nt < 4; nt++) {
        int oc0 = wn*32 + nt*8 + 2*t4;
        int oc1 = oc0 + 1;
        out[((size_t)b*C2 + oc0)*HW2 + p0] = acc[nt][0];
        out[((size_t)b*C2 + oc1)*HW2 + p0] = acc[nt][1];
        out[((size_t)b*C2 + oc0)*HW2 + p1] = acc[nt][2];
        out[((size_t)b*C2 + oc1)*HW2 + p1] = acc[nt][3];
    }
}

// ---------------- launch ----------------
extern "C" void kernel_launch(void* const* d_in, const int* in_sizes, int n_in,
                              void* d_out, int out_size)
{
    const float* x       = (const float*)d_in[0];
    const float* conv1_w = (const float*)d_in[1];
    const float* conv1_b = (const float*)d_in[2];
    const float* bn1_g   = (const float*)d_in[3];
    const float* bn1_b   = (const float*)d_in[4];
    const float* conv2_w = (const float*)d_in[5];
    const float* conv2_b = (const float*)d_in[6];
    const float* bn2_g   = (const float*)d_in[7];
    const float* bn2_b   = (const float*)d_in[8];
    const float* off_w   = (const float*)d_in[9];
    const float* off_b   = (const float*)d_in[10];
    const float* conv4_w = (const float*)d_in[11];
    float* out = (float*)d_out;

    float *p_s1, *p_t1, *p_s2, *p_t2, *p_h2pad;
    float *p_p1s, *p_p1q, *p_p2s, *p_p2q;
    unsigned *p_w2h, *p_w2l, *p_w4h, *p_w4l, *p_wOh, *p_wOl;
    cudaGetSymbolAddress((void**)&p_s1,    g_scale1);
    cudaGetSymbolAddress((void**)&p_t1,    g_shift1);
    cudaGetSymbolAddress((void**)&p_s2,    g_scale2);
    cudaGetSymbolAddress((void**)&p_t2,    g_shift2);
    cudaGetSymbolAddress((void**)&p_h2pad, g_h2pad);
    cudaGetSymbolAddress((void**)&p_p1s,   g_p1s);
    cudaGetSymbolAddress((void**)&p_p1q,   g_p1q);
    cudaGetSymbolAddress((void**)&p_p2s,   g_p2s);
    cudaGetSymbolAddress((void**)&p_p2q,   g_p2q);
    cudaGetSymbolAddress((void**)&p_w2h,   g_w2h);
    cudaGetSymbolAddress((void**)&p_w2l,   g_w2l);
    cudaGetSymbolAddress((void**)&p_w4h,   g_w4h);
    cudaGetSymbolAddress((void**)&p_w4l,   g_w4l);
    cudaGetSymbolAddress((void**)&p_wOh,   g_wOh);
    cudaGetSymbolAddress((void**)&p_wOl,   g_wOl);

    const int SMEM_CONV2  = (72*XS + 2*72*WS) * 4 + 2*C1*4;                 // ~90.4 KB
    const int SMEM_OFFS   = (72*XSO + 2*72*WSO) * 4 + 2*C2*4;               // ~62.2 KB
    const int SMEM_DEFORM = (72*XS + 2*72*WS) * 4 + (4*288*2 + 288 + 2*C2)*4; // ~99.9 KB
    cudaFuncSetAttribute(conv2_mma_kernel,
                         cudaFuncAttributeMaxDynamicSharedMemorySize, SMEM_CONV2);
    cudaFuncSetAttribute(offs_mma_kernel,
                         cudaFuncAttributeMaxDynamicSharedMemorySize, SMEM_OFFS);
    cudaFuncSetAttribute(deform_mma_kernel,
                         cudaFuncAttributeMaxDynamicSharedMemorySize, SMEM_DEFORM);

    // 0) weight preprocessing
    split_w_kernel<<<(C2*C1*9 + 255)/256, 256>>>(conv2_w, p_w2h, p_w2l, C1, C2);
    split_w_kernel<<<(C2*C2*9 + 255)/256, 256>>>(conv4_w, p_w4h, p_w4l, C2, C2);
    split_w_pad_kernel<<<(C2*9*32 + 255)/256, 256>>>(off_w, p_wOh, p_wOl);

    // 1) conv1 + bias + relu + BN1 partials + 2x2 pool -> raw padded pooled
    {
        dim3 grid(196, 4, BATCH);
        conv1_fused_kernel<<<grid, 128>>>(x, conv1_w, conv1_b);
    }
    // 2) BN1 finalize
    bn_finalize_kernel<<<C1, 256>>>(p_p1s, p_p1q, bn1_g, bn1_b, p_s1, p_t1,
                                    784, 1.0f/(float)(BATCH*H1*W1));
    // 3) conv2 MMA (BN1 folded in gather) -> raw padded h2 + BN2 partials
    conv2_mma_kernel<<<GBLK, 256, SMEM_CONV2>>>(conv2_b, p_h2pad);
    // 4) BN2 finalize
    bn_finalize_kernel<<<C2, 256>>>(p_p2s, p_p2q, bn2_g, bn2_b, p_s2, p_t2,
                                    GBLK, 1.0f/(float)(BATCH*HW2));
    // 5) offsets conv MMA (BN2 folded in gather)
    offs_mma_kernel<<<BATCH*NOFF, 256, SMEM_OFFS>>>(off_b);
    // 6) deformable conv MMA (BN2 folded in bilinear gather) -> d_out
    deform_mma_kernel<<<GBLK, 256, SMEM_DEFORM>>>(out);
}

// round 7
// speedup vs baseline: 1.7180x; 1.1688x over previous
#include <cuda_runtime.h>
#include <math.h>

// ---------------- problem constants ----------------
#define BATCH 4
#define C1    64
#define H1    224
#define W1    224
#define C2    128
#define H2    112
#define W2    112
#define HP    114
#define WP    114
#define HW2   (H2*W2)      // 12544
#define HWP   (HP*WP)      // 12996
#define COFF  18
#define K2    (C1*9)       // 576
#define K4    (C2*9)       // 1152
#define NT128 98           // 128-px tiles per image
#define GB2   (BATCH*NT128) // 392 GEMM blocks
#define NOFF  98

// offsets-kernel smem strides
#define XSO 136
#define WSO 40

// ---------------- scratch (__device__ globals; zero-init, no allocation) ----------------
__device__ float    g_poolpad[BATCH*C1*HWP];   // raw pooled conv1+relu, zero border
__device__ float    g_h2pad[BATCH*C2*HWP];     // raw relu(conv2+bias), zero border
__device__ float    g_offs[BATCH*COFF*HW2];
__device__ float    g_x2  [(size_t)BATCH*K2*HW2];   // conv2 im2col (tf32-rounded, BN1 folded)
__device__ float    g_xoff[(size_t)BATCH*K4*HW2];   // deform gather (tf32-rounded, BN2 folded)
__device__ unsigned g_bxy [BATCH*9*HW2];            // packed corner coords
__device__ float4   g_bw4 [BATCH*9*HW2];            // bilinear corner weights
__device__ float    g_bts [BATCH*9*HW2];            // interior-masked weight sum
__device__ unsigned g_w2h[K2*C2],  g_w2l[K2*C2];    // conv2 W^T tf32 hi/lo [ic*9+n][oc]
__device__ unsigned g_w4h[K4*C2],  g_w4l[K4*C2];    // conv4 W^T tf32 hi/lo
__device__ unsigned g_wOh[K4*32],  g_wOl[K4*32];    // offsets W^T padded to 32 oc
__device__ float    g_p1s[C1*784], g_p1q[C1*784];   // BN1 per-block partials
__device__ float    g_p2s[C2*GB2], g_p2q[C2*GB2];   // BN2 per-block partials
__device__ float    g_scale1[C1], g_shift1[C1];
__device__ float    g_scale2[C2], g_shift2[C2];

// ---------------- helpers ----------------
__device__ __forceinline__ unsigned f2tf32(float f) {
    unsigned r; asm("cvt.rna.tf32.f32 %0, %1;" : "=r"(r) : "f"(f)); return r;
}
__device__ __forceinline__ void mma_tf32(float& d0, float& d1, float& d2, float& d3,
                                         unsigned a0, unsigned a1, unsigned a2, unsigned a3,
                                         unsigned b0, unsigned b1) {
    asm volatile("mma.sync.aligned.m16n8k8.row.col.f32.tf32.tf32.f32 "
                 "{%0,%1,%2,%3},{%4,%5,%6,%7},{%8,%9},{%0,%1,%2,%3};"
                 : "+f"(d0), "+f"(d1), "+f"(d2), "+f"(d3)
                 : "r"(a0), "r"(a1), "r"(a2), "r"(a3), "r"(b0), "r"(b1));
}
__device__ __forceinline__ void cp16(void* dst, const void* src) {
    unsigned d = (unsigned)__cvta_generic_to_shared(dst);
    asm volatile("cp.async.cg.shared.global [%0], [%1], 16;" :: "r"(d), "l"(src));
}
__device__ __forceinline__ void cp_commit() { asm volatile("cp.async.commit_group;"); }
__device__ __forceinline__ void cp_wait0()  { asm volatile("cp.async.wait_group 0;" ::: "memory"); }

// ---------------- weight transpose + tf32 hi/lo split ----------------
__global__ void __launch_bounds__(256)
split_w_kernel(const float* __restrict__ w, unsigned* __restrict__ wh,
               unsigned* __restrict__ wl, int C_in, int C_out)
{
    int idx = blockIdx.x * 256 + threadIdx.x;
    int total = C_out * C_in * 9;
    if (idx >= total) return;
    int oc = idx % C_out;
    int r  = idx / C_out;
    int ic = r / 9, n = r % 9;
    float v = w[((size_t)oc*C_in + ic)*9 + n];
    unsigned h = f2tf32(v);
    wh[idx] = h;
    wl[idx] = f2tf32(v - __uint_as_float(h));
}

__global__ void __launch_bounds__(256)
split_w_pad_kernel(const float* __restrict__ w, unsigned* __restrict__ wh,
                   unsigned* __restrict__ wl)
{
    int idx = blockIdx.x * 256 + threadIdx.x;
    int total = K4 * 32;
    if (idx >= total) return;
    int oc = idx % 32;
    int r  = idx / 32;
    int ic = r / 9, n = r % 9;
    float v = (oc < COFF) ? w[((size_t)oc*C2 + ic)*9 + n] : 0.f;
    unsigned h = f2tf32(v);
    wh[idx] = h;
    wl[idx] = f2tf32(v - __uint_as_float(h));
}

// ---------------- conv1 fused: conv + bias + relu + BN1 partials + 2x2 pool ----------------
__global__ void __launch_bounds__(128)
conv1_fused_kernel(const float* __restrict__ x, const float* __restrict__ wgt,
                   const float* __restrict__ bias)
{
    __shared__ float s_in[3][18][18];
    __shared__ float s_w[16][3][9];
    __shared__ float s_red[2][16][4];

    const int tileX  = (blockIdx.x % 14) * 16;
    const int tileY  = (blockIdx.x / 14) * 16;
    const int ocBase = blockIdx.y * 16;
    const int b      = blockIdx.z;
    const int tid    = threadIdx.x;
    const int tx     = tid & 15;
    const int ty     = tid >> 4;

    for (int e = tid; e < 3*18*18; e += 128) {
        int ic = e / 324;
        int r  = (e / 18) % 18;
        int c  = e % 18;
        int gy = tileY + r - 1, gx = tileX + c - 1;
        float v = 0.f;
        if (gy >= 0 && gy < H1 && gx >= 0 && gx < W1)
            v = x[(((size_t)b*3 + ic)*H1 + gy)*W1 + gx];
        s_in[ic][r][c] = v;
    }
    for (int e = tid; e < 16*27; e += 128) {
        int oc = e / 27, r = e % 27;
        int ic = r / 9, k = r % 9;
        s_w[oc][ic][k] = wgt[((size_t)(ocBase+oc)*3 + ic)*9 + k];
    }
    __syncthreads();

    float acc0[16], acc1[16];
#pragma unroll
    for (int i = 0; i < 16; i++) { acc0[i] = 0.f; acc1[i] = 0.f; }
    const int y0 = ty * 2;
#pragma unroll
    for (int ic = 0; ic < 3; ic++) {
        float r[4][3];
#pragma unroll
        for (int rr = 0; rr < 4; rr++)
#pragma unroll
            for (int cc = 0; cc < 3; cc++)
                r[rr][cc] = s_in[ic][y0+rr][tx+cc];
#pragma unroll
        for (int oc = 0; oc < 16; oc++) {
            float a0 = acc0[oc], a1 = acc1[oc];
#pragma unroll
            for (int k = 0; k < 9; k++) {
                float wv = s_w[oc][ic][k];
                a0 = fmaf(r[k/3  ][k%3], wv, a0);
                a1 = fmaf(r[k/3+1][k%3], wv, a1);
            }
            acc0[oc] = a0; acc1[oc] = a1;
        }
    }

    const int warp = tid >> 5, lane = tid & 31;
    const int prow = (tileY >> 1) + ty + 1;
    const int pcol = (tileX >> 1) + (tx >> 1) + 1;
    const int blkId = blockIdx.x + 196 * blockIdx.z;

#pragma unroll
    for (int oc = 0; oc < 16; oc++) {
        float bv = bias[ocBase + oc];
        float v0 = fmaxf(acc0[oc] + bv, 0.f);
        float v1 = fmaxf(acc1[oc] + bv, 0.f);
        float pv = v0 + v1;
        float po = pv + __shfl_xor_sync(0xffffffffu, pv, 1);
        if ((tx & 1) == 0)
            g_poolpad[(((size_t)b*C1 + ocBase + oc)*HP + prow)*WP + pcol] = 0.25f * po;
        float s = pv, q = v0*v0 + v1*v1;
#pragma unroll
        for (int o = 16; o; o >>= 1) {
            s += __shfl_down_sync(0xffffffffu, s, o);
            q += __shfl_down_sync(0xffffffffu, q, o);
        }
        if (lane == 0) { s_red[0][oc][warp] = s; s_red[1][oc][warp] = q; }
    }
    __syncthreads();
    if (tid < 16) {
        float S = s_red[0][tid][0] + s_red[0][tid][1] + s_red[0][tid][2] + s_red[0][tid][3];
        float Q = s_red[1][tid][0] + s_red[1][tid][1] + s_red[1][tid][2] + s_red[1][tid][3];
        g_p1s[(size_t)(ocBase + tid)*784 + blkId] = S;
        g_p1q[(size_t)(ocBase + tid)*784 + blkId] = Q;
    }
}

// ---------------- BN finalize ----------------
__global__ void __launch_bounds__(256)
bn_finalize_kernel(const float* __restrict__ ps, const float* __restrict__ pq,
                   const float* __restrict__ gamma, const float* __restrict__ beta,
                   float* __restrict__ scale, float* __restrict__ shift,
                   int nblk, float inv_count)
{
    const int c = blockIdx.x;
    const int tid = threadIdx.x;
    float s = 0.f, q = 0.f;
    for (int i = tid; i < nblk; i += 256) {
        s += ps[(size_t)c*nblk + i];
        q += pq[(size_t)c*nblk + i];
    }
    __shared__ float sh[64];
#pragma unroll
    for (int o = 16; o; o >>= 1) {
        s += __shfl_down_sync(0xffffffffu, s, o);
        q += __shfl_down_sync(0xffffffffu, q, o);
    }
    int warp = tid >> 5, lane = tid & 31;
    if (lane == 0) { sh[warp] = s; sh[32+warp] = q; }
    __syncthreads();
    if (warp == 0) {
        s = (lane < 8) ? sh[lane]    : 0.f;
        q = (lane < 8) ? sh[32+lane] : 0.f;
#pragma unroll
        for (int o = 4; o; o >>= 1) {
            s += __shfl_down_sync(0xffffffffu, s, o);
            q += __shfl_down_sync(0xffffffffu, q, o);
        }
        if (lane == 0) {
            float mean = s * inv_count;
            float var  = q * inv_count - mean*mean;
            float inv  = rsqrtf(var + 1e-5f);
            float sc   = gamma[c] * inv;
            scale[c] = sc;
            shift[c] = beta[c] - mean * sc;
        }
    }
}

// ---------------- conv2 im2col with BN1 fold -> g_x2 (tf32-rounded) ----------------
__global__ void __launch_bounds__(256)
x2col_kernel()
{
    const int hw = blockIdx.x * 256 + threadIdx.x;   // 12544 < 49*256
    const int r  = blockIdx.y;                       // 0..575
    const int b  = blockIdx.z;
    if (hw >= HW2) return;
    const int ic = r / 9, n = r % 9;
    const int h = hw / W2, w = hw - h*W2;
    const int hh = h + n/3, ww = w + n%3;
    float raw = g_poolpad[((size_t)(b*C1 + ic))*HWP + hh*WP + ww];
    float m = ((unsigned)(hh-1) < 112u && (unsigned)(ww-1) < 112u) ? 1.f : 0.f;
    float v = raw * g_scale1[ic] + m * g_shift1[ic];
    g_x2[((size_t)b*K2 + r)*HW2 + hw] = __uint_as_float(f2tf32(v));
}

// ---------------- bilinear params per (b, tap, px) ----------------
__global__ void __launch_bounds__(256)
bilin_params_kernel()
{
    int idx = blockIdx.x * 256 + threadIdx.x;
    if (idx >= BATCH*9*HW2) return;
    int hw = idx % HW2;
    int n  = (idx / HW2) % 9;
    int b  = idx / (9*HW2);
    int h = hw / W2, w = hw - h*W2;
    float ox = g_offs[((size_t)b*COFF + n)     * HW2 + hw];
    float oy = g_offs[((size_t)b*COFF + 9 + n) * HW2 + hw];
    float pX = (float)(h + 1) + (float)(n/3 - 1) + ox;
    float pY = (float)(w + 1) + (float)(n%3 - 1) + oy;
    float fx = floorf(pX), fy = floorf(pY);
    float qltx = fminf(fmaxf(fx,     0.f), (float)(HP-1));
    float qlty = fminf(fmaxf(fy,     0.f), (float)(WP-1));
    float qrbx = fminf(fmaxf(fx+1.f, 0.f), (float)(HP-1));
    float qrby = fminf(fmaxf(fy+1.f, 0.f), (float)(WP-1));
    bool mx = (pX < 1.f) || (pX > (float)(HP-2));
    bool my = (pY < 1.f) || (pY > (float)(WP-2));
    float pxc = fminf(fmaxf(mx ? fx : pX, 0.f), (float)(HP-1));
    float pyc = fminf(fmaxf(my ? fy : pY, 0.f), (float)(WP-1));
    float glt = (1.f + (qltx - pxc)) * (1.f + (qlty - pyc));
    float grb = (1.f - (qrbx - pxc)) * (1.f - (qrby - pyc));
    float glb = (1.f + (qltx - pxc)) * (1.f - (qrby - pyc));
    float grt = (1.f - (qrbx - pxc)) * (1.f + (qlty - pyc));
    int ix0 = (int)qltx, iy0 = (int)qlty;
    int ix1 = (int)qrbx, iy1 = (int)qrby;
    float m0 = ((unsigned)(ix0-1) < 112u && (unsigned)(iy0-1) < 112u) ? 1.f : 0.f;
    float m1 = ((unsigned)(ix1-1) < 112u && (unsigned)(iy1-1) < 112u) ? 1.f : 0.f;
    float m2 = ((unsigned)(ix0-1) < 112u && (unsigned)(iy1-1) < 112u) ? 1.f : 0.f;
    float m3 = ((unsigned)(ix1-1) < 112u && (unsigned)(iy0-1) < 112u) ? 1.f : 0.f;
    g_bxy[idx] = (unsigned)ix0 | ((unsigned)iy0 << 8) | ((unsigned)ix1 << 16) | ((unsigned)iy1 << 24);
    g_bw4[idx] = make_float4(glt, grb, glb, grt);
    g_bts[idx] = glt*m0 + grb*m1 + glb*m2 + grt*m3;
}

// ---------------- deform gather: bilinear + BN2 fold -> g_xoff (tf32-rounded) ----------------
__global__ void __launch_bounds__(256)
xoff_kernel()
{
    __shared__ float s_s[C2], s_t[C2];
    const int tid = threadIdx.x;
    const int hw  = blockIdx.x * 256 + tid;
    const int n   = blockIdx.y;
    const int b   = blockIdx.z;
    if (tid < C2) { s_s[tid] = g_scale2[tid]; s_t[tid] = g_shift2[tid]; }
    __syncthreads();
    if (hw >= HW2) return;

    const int idx = (b*9 + n)*HW2 + hw;
    unsigned xy = g_bxy[idx];
    float4 bw   = g_bw4[idx];
    float  ts   = g_bts[idx];
    int ix0 = xy & 255, iy0 = (xy >> 8) & 255, ix1 = (xy >> 16) & 255, iy1 = xy >> 24;
    int i00 = ix0*WP + iy0;
    int i11 = ix1*WP + iy1;
    int i01 = ix0*WP + iy1;
    int i10 = ix1*WP + iy0;

    const float* base = g_h2pad + (size_t)b*C2*HWP;
    float* outp = g_xoff + ((size_t)b*K4 + n)*HW2 + hw;
#pragma unroll 4
    for (int ic = 0; ic < C2; ic++) {
        const float* plane = base + (size_t)ic*HWP;
        float raw = bw.x * __ldg(plane + i00)
                  + bw.y * __ldg(plane + i11)
                  + bw.z * __ldg(plane + i01)
                  + bw.w * __ldg(plane + i10);
        float v = raw * s_s[ic] + ts * s_t[ic];
        outp[(size_t)ic*9*HW2] = __uint_as_float(f2tf32(v));
    }
}

// ---------------- double-buffered tf32-2x MMA GEMM: 128px x 128oc, kchunk=48 ----------------
// X: [b][K][HW2] pre-rounded tf32; W^T hi/lo: [K][128]
template<int NCHUNK, bool CONV2EPI>
__global__ void __launch_bounds__(256, 1)
gemm_mma_kernel(const float* __restrict__ X, const unsigned* __restrict__ Wh,
                const unsigned* __restrict__ Wl, const float* __restrict__ bias,
                float* __restrict__ out)
{
    extern __shared__ unsigned smem_u[];
    // layout (words): s_x[2][48*136], s_wh[2][48*136], s_wl[2][48*136]
    const int SB = 48*136;   // 6528

    const int tid = threadIdx.x;
    const int blk = blockIdx.x;              // 392
    const int b   = blk / NT128;
    const int hw0 = (blk % NT128) * 128;
    const int lane = tid & 31, wid = tid >> 5;
    const int g = lane >> 2, t4 = lane & 3;

    const float* Xb = X + (size_t)b*(NCHUNK*48)*HW2 + hw0;

    // prefetch chunk 0
    {
        unsigned* sx = smem_u;
        for (int e = tid; e < 1536; e += 256) {
            int row = e >> 5, c = (e & 31) * 4;
            cp16(sx + row*136 + c, Xb + (size_t)row*HW2 + c);
        }
        unsigned* swh = smem_u + 2*SB;
        unsigned* swl = smem_u + 4*SB;
        const uint4* h4 = (const uint4*)Wh;
        const uint4* l4 = (const uint4*)Wl;
        for (int e = tid; e < 1536; e += 256) {
            int row = e >> 5, c4 = e & 31;
            cp16(swh + row*136 + c4*4, h4 + e);
            cp16(swl + row*136 + c4*4, l4 + e);
        }
        cp_commit();
    }

    float acc[16][4] = {};

    for (int c = 0; c < NCHUNK; c++) {
        const int buf = c & 1;
        cp_wait0();
        __syncthreads();
        if (c + 1 < NCHUNK) {
            const int nb = buf ^ 1;
            const int k0 = (c + 1) * 48;
            unsigned* sx = smem_u + nb*SB;
            for (int e = tid; e < 1536; e += 256) {
                int row = e >> 5, cc = (e & 31) * 4;
                cp16(sx + row*136 + cc, Xb + (size_t)(k0+row)*HW2 + cc);
            }
            unsigned* swh = smem_u + 2*SB + nb*SB;
            unsigned* swl = smem_u + 4*SB + nb*SB;
            const uint4* h4 = (const uint4*)(Wh + (size_t)k0*C2);
            const uint4* l4 = (const uint4*)(Wl + (size_t)k0*C2);
            for (int e = tid; e < 1536; e += 256) {
                int row = e >> 5, c4 = e & 31;
                cp16(swh + row*136 + c4*4, h4 + e);
                cp16(swl + row*136 + c4*4, l4 + e);
            }
            cp_commit();
        }

        const unsigned* sx  = smem_u + buf*SB;
        const unsigned* swh = smem_u + 2*SB + buf*SB;
        const unsigned* swl = smem_u + 4*SB + buf*SB;
#pragma unroll
        for (int ks = 0; ks < 6; ks++) {
            const unsigned* xp = sx + (ks*8 + t4)*136 + wid*16 + g;
            unsigned a0 = xp[0], a1 = xp[8], a2 = xp[4*136], a3 = xp[4*136+8];
            const unsigned* wh = swh + (ks*8 + t4)*136 + g;
            const unsigned* wl = swl + (ks*8 + t4)*136 + g;
#pragma unroll
            for (int nt = 0; nt < 16; nt++) {
                unsigned bh0 = wh[nt*8], bh1 = wh[4*136 + nt*8];
                unsigned bl0 = wl[nt*8], bl1 = wl[4*136 + nt*8];
                mma_tf32(acc[nt][0],acc[nt][1],acc[nt][2],acc[nt][3], a0,a1,a2,a3, bh0,bh1);
                mma_tf32(acc[nt][0],acc[nt][1],acc[nt][2],acc[nt][3], a0,a1,a2,a3, bl0,bl1);
            }
        }
        __syncthreads();
    }

    const int p0 = hw0 + wid*16 + g;
    const int p1 = p0 + 8;

    if (CONV2EPI) {
        // bias + relu -> padded plane interior; BN2 partials
        float* s_red = (float*)smem_u;    // [8][128][2]
        const int h0 = p0 / W2, w0 = p0 - h0*W2;
        const int h1 = p1 / W2, w1 = p1 - h1*W2;
#pragma unroll
        for (int nt = 0; nt < 16; nt++) {
            int oc0 = nt*8 + 2*t4;
            int oc1 = oc0 + 1;
            float b0v = bias[oc0], b1v = bias[oc1];
            float v00 = fmaxf(acc[nt][0] + b0v, 0.f);
            float v01 = fmaxf(acc[nt][1] + b1v, 0.f);
            float v10 = fmaxf(acc[nt][2] + b0v, 0.f);
            float v11 = fmaxf(acc[nt][3] + b1v, 0.f);
            out[(((size_t)b*C2 + oc0)*HP + h0+1)*WP + w0+1] = v00;
            out[(((size_t)b*C2 + oc1)*HP + h0+1)*WP + w0+1] = v01;
            out[(((size_t)b*C2 + oc0)*HP + h1+1)*WP + w1+1] = v10;
            out[(((size_t)b*C2 + oc1)*HP + h1+1)*WP + w1+1] = v11;
            float s0 = v00 + v10, q0 = v00*v00 + v10*v10;
            float s1 = v01 + v11, q1 = v01*v01 + v11*v11;
#pragma unroll
            for (int o = 4; o <= 16; o <<= 1) {
                s0 += __shfl_xor_sync(0xffffffffu, s0, o);
                q0 += __shfl_xor_sync(0xffffffffu, q0, o);
                s1 += __shfl_xor_sync(0xffffffffu, s1, o);
                q1 += __shfl_xor_sync(0xffffffffu, q1, o);
            }
            if (g == 0) {
                s_red[(wid*128 + oc0)*2 + 0] = s0;
                s_red[(wid*128 + oc0)*2 + 1] = q0;
                s_red[(wid*128 + oc1)*2 + 0] = s1;
                s_red[(wid*128 + oc1)*2 + 1] = q1;
            }
        }
        __syncthreads();
        if (tid < 128) {
            float S = 0.f, Q = 0.f;
#pragma unroll
            for (int w = 0; w < 8; w++) {
                S += s_red[(w*128 + tid)*2 + 0];
                Q += s_red[(w*128 + tid)*2 + 1];
            }
            g_p2s[(size_t)tid*GB2 + blk] = S;
            g_p2q[(size_t)tid*GB2 + blk] = Q;
        }
    } else {
#pragma unroll
        for (int nt = 0; nt < 16; nt++) {
            int oc0 = nt*8 + 2*t4;
            int oc1 = oc0 + 1;
            out[((size_t)b*C2 + oc0)*HW2 + p0] = acc[nt][0];
            out[((size_t)b*C2 + oc1)*HW2 + p0] = acc[nt][1];
            out[((size_t)b*C2 + oc0)*HW2 + p1] = acc[nt][2];
            out[((size_t)b*C2 + oc1)*HW2 + p1] = acc[nt][3];
        }
    }
}

// ---------------- offsets conv: tf32-2x MMA, 128px x 32oc(pad 18), BN2 folded ----------------
__global__ void __launch_bounds__(256)
offs_mma_kernel(const float* __restrict__ bias)
{
    extern __shared__ unsigned smem_u[];
    unsigned* s_x  = smem_u;
    unsigned* s_wh = s_x  + 72*XSO;
    unsigned* s_wl = s_wh + 72*WSO;
    float*    s_s  = (float*)(s_wl + 72*WSO);
    float*    s_t  = s_s + C2;

    const int tid  = threadIdx.x;
    const int blk  = blockIdx.x;
    const int b    = blk / NOFF;
    const int hw0  = (blk % NOFF) * 128;
    const int lane = tid & 31, wid = tid >> 5;
    const int g    = lane >> 2, t4 = lane & 3;
    const int px0  = wid * 16;

    if (tid < C2) { s_s[tid] = g_scale2[tid]; s_t[tid] = g_shift2[tid]; }

    const float* inb = g_h2pad + (size_t)b*C2*HWP;
    float acc[4][4] = {};

    for (int ic0 = 0; ic0 < C2; ic0 += 8) {
        __syncthreads();
        {
            const uint4* sh4 = (const uint4*)(g_wOh + (size_t)ic0*9*32);
            const uint4* sl4 = (const uint4*)(g_wOl + (size_t)ic0*9*32);
            for (int e = tid; e < 576; e += 256) {
                int kr = e >> 3, c4 = e & 7;
                cp16(s_wh + kr*WSO + c4*4, sh4 + e);
                cp16(s_wl + kr*WSO + c4*4, sl4 + e);
            }
        }
        for (int e = tid; e < 9216; e += 256) {
            int r  = e >> 7, px = e & 127;
            int icr = r / 9, n = r - icr*9;
            int hw = hw0 + px;
            int h  = hw / W2, w = hw - h*W2;
            int hh = h + n/3, ww = w + n%3;
            float raw = inb[(size_t)(ic0+icr)*HWP + hh*WP + ww];
            float m = ((unsigned)(hh-1) < 112u && (unsigned)(ww-1) < 112u) ? 1.f : 0.f;
            float v = raw * s_s[ic0+icr] + m * s_t[ic0+icr];
            s_x[r*XSO + px] = f2tf32(v);
        }
        cp_commit(); cp_wait0();
        __syncthreads();

#pragma unroll
        for (int ks = 0; ks < 9; ks++) {
            const unsigned* xp = s_x + (ks*8 + t4)*XSO + px0 + g;
            unsigned a0 = xp[0], a1 = xp[8], a2 = xp[4*XSO], a3 = xp[4*XSO+8];
            const unsigned* wh = s_wh + (ks*8 + t4)*WSO + g;
            const unsigned* wl = s_wl + (ks*8 + t4)*WSO + g;
#pragma unroll
            for (int nt = 0; nt < 4; nt++) {
                unsigned bh0 = wh[nt*8], bh1 = wh[4*WSO + nt*8];
                unsigned bl0 = wl[nt*8], bl1 = wl[4*WSO + nt*8];
                mma_tf32(acc[nt][0],acc[nt][1],acc[nt][2],acc[nt][3], a0,a1,a2,a3, bh0,bh1);
                mma_tf32(acc[nt][0],acc[nt][1],acc[nt][2],acc[nt][3], a0,a1,a2,a3, bl0,bl1);
            }
        }
    }

    const int p0 = hw0 + px0 + g, p1 = p0 + 8;
#pragma unroll
    for (int nt = 0; nt < 4; nt++) {
        int oc0 = nt*8 + 2*t4;
        int oc1 = oc0 + 1;
        if (oc0 < COFF) {
            float bv = bias[oc0];
            g_offs[((size_t)b*COFF + oc0)*HW2 + p0] = acc[nt][0] + bv;
            g_offs[((size_t)b*COFF + oc0)*HW2 + p1] = acc[nt][2] + bv;
        }
        if (oc1 < COFF) {
            float bv = bias[oc1];
            g_offs[((size_t)b*COFF + oc1)*HW2 + p0] = acc[nt][1] + bv;
            g_offs[((size_t)b*COFF + oc1)*HW2 + p1] = acc[nt][3] + bv;
        }
    }
}

// ---------------- launch ----------------
extern "C" void kernel_launch(void* const* d_in, const int* in_sizes, int n_in,
                              void* d_out, int out_size)
{
    const float* x       = (const float*)d_in[0];
    const float* conv1_w = (const float*)d_in[1];
    const float* conv1_b = (const float*)d_in[2];
    const float* bn1_g   = (const float*)d_in[3];
    const float* bn1_b   = (const float*)d_in[4];
    const float* conv2_w = (const float*)d_in[5];
    const float* conv2_b = (const float*)d_in[6];
    const float* bn2_g   = (const float*)d_in[7];
    const float* bn2_b   = (const float*)d_in[8];
    const float* off_w   = (const float*)d_in[9];
    const float* off_b   = (const float*)d_in[10];
    const float* conv4_w = (const float*)d_in[11];
    float* out = (float*)d_out;

    float *p_s1, *p_t1, *p_s2, *p_t2, *p_h2pad, *p_x2, *p_xoff;
    float *p_p1s, *p_p1q, *p_p2s, *p_p2q;
    unsigned *p_w2h, *p_w2l, *p_w4h, *p_w4l, *p_wOh, *p_wOl;
    cudaGetSymbolAddress((void**)&p_s1,    g_scale1);
    cudaGetSymbolAddress((void**)&p_t1,    g_shift1);
    cudaGetSymbolAddress((void**)&p_s2,    g_scale2);
    cudaGetSymbolAddress((void**)&p_t2,    g_shift2);
    cudaGetSymbolAddress((void**)&p_h2pad, g_h2pad);
    cudaGetSymbolAddress((void**)&p_x2,    g_x2);
    cudaGetSymbolAddress((void**)&p_xoff,  g_xoff);
    cudaGetSymbolAddress((void**)&p_p1s,   g_p1s);
    cudaGetSymbolAddress((void**)&p_p1q,   g_p1q);
    cudaGetSymbolAddress((void**)&p_p2s,   g_p2s);
    cudaGetSymbolAddress((void**)&p_p2q,   g_p2q);
    cudaGetSymbolAddress((void**)&p_w2h,   g_w2h);
    cudaGetSymbolAddress((void**)&p_w2l,   g_w2l);
    cudaGetSymbolAddress((void**)&p_w4h,   g_w4h);
    cudaGetSymbolAddress((void**)&p_w4l,   g_w4l);
    cudaGetSymbolAddress((void**)&p_wOh,   g_wOh);
    cudaGetSymbolAddress((void**)&p_wOl,   g_wOl);

    const int SMEM_GEMM = 6 * 48 * 136 * 4;                    // 156672
    const int SMEM_OFFS = (72*XSO + 2*72*WSO) * 4 + 2*C2*4;
    cudaFuncSetAttribute(gemm_mma_kernel<12, true>,
                         cudaFuncAttributeMaxDynamicSharedMemorySize, SMEM_GEMM);
    cudaFuncSetAttribute(gemm_mma_kernel<24, false>,
                         cudaFuncAttributeMaxDynamicSharedMemorySize, SMEM_GEMM);
    cudaFuncSetAttribute(offs_mma_kernel,
                         cudaFuncAttributeMaxDynamicSharedMemorySize, SMEM_OFFS);

    // 0) weight preprocessing
    split_w_kernel<<<(C2*C1*9 + 255)/256, 256>>>(conv2_w, p_w2h, p_w2l, C1, C2);
    split_w_kernel<<<(C2*C2*9 + 255)/256, 256>>>(conv4_w, p_w4h, p_w4l, C2, C2);
    split_w_pad_kernel<<<(K4*32 + 255)/256, 256>>>(off_w, p_wOh, p_wOl);

    // 1) conv1 + bias + relu + BN1 partials + 2x2 pool
    {
        dim3 grid(196, 4, BATCH);
        conv1_fused_kernel<<<grid, 128>>>(x, conv1_w, conv1_b);
    }
    // 2) BN1 finalize
    bn_finalize_kernel<<<C1, 256>>>(p_p1s, p_p1q, bn1_g, bn1_b, p_s1, p_t1,
                                    784, 1.0f/(float)(BATCH*H1*W1));
    // 3) conv2 im2col (BN1 folded)
    {
        dim3 grid(49, K2, BATCH);
        x2col_kernel<<<grid, 256>>>();
    }
    // 4) conv2 GEMM -> raw padded h2 + BN2 partials
    gemm_mma_kernel<12, true><<<GB2, 256, SMEM_GEMM>>>(p_x2, p_w2h, p_w2l,
                                                       conv2_b, p_h2pad);
    // 5) BN2 finalize
    bn_finalize_kernel<<<C2, 256>>>(p_p2s, p_p2q, bn2_g, bn2_b, p_s2, p_t2,
                                    GB2, 1.0f/(float)(BATCH*HW2));
    // 6) offsets conv (BN2 folded in gather)
    offs_mma_kernel<<<BATCH*NOFF, 256, SMEM_OFFS>>>(off_b);
    // 7) bilinear params
    bilin_params_kernel<<<(BATCH*9*HW2 + 255)/256, 256>>>();
    // 8) deform gather (BN2 folded) -> g_xoff
    {
        dim3 grid(49, 9, BATCH);
        xoff_kernel<<<grid, 256>>>();
    }
    // 9) deform GEMM -> d_out
    gemm_mma_kernel<24, false><<<GB2, 256, SMEM_GEMM>>>(p_xoff, p_w4h, p_w4l,
                                                        nullptr, out);
}

// round 8
// speedup vs baseline: 2.0862x; 1.2144x over previous
#include <cuda_runtime.h>
#include <math.h>

// ---------------- problem constants ----------------
#define BATCH 4
#define C1    64
#define H1    224
#define W1    224
#define C2    128
#define H2    112
#define W2    112
#define HP    114
#define WP    114
#define HW2   (H2*W2)      // 12544
#define HWP   (HP*WP)      // 12996
#define COFF  18
#define K2    (C1*9)       // 576
#define K4    (C2*9)       // 1152
#define NT128 98           // 128-px tiles per image
#define GB2   (BATCH*NT128) // 392 GEMM blocks
#define NOFF  98

// offsets-kernel smem strides
#define XSO 136
#define WSO 40

// ---------------- scratch (__device__ globals; zero-init, no allocation) ----------------
__device__ float    g_poolpad[BATCH*C1*HWP];   // raw pooled conv1+relu, zero border
__device__ float    g_h2pad[BATCH*C2*HWP];     // raw relu(conv2+bias), zero border
__device__ float    g_offs[BATCH*COFF*HW2];
__device__ float    g_x2  [(size_t)BATCH*K2*HW2];   // conv2 im2col (tf32-rounded, BN1 folded)
__device__ float    g_xoff[(size_t)BATCH*K4*HW2];   // deform gather (tf32-rounded, BN2 folded)
__device__ unsigned g_bxy [BATCH*9*HW2];            // packed corner coords
__device__ float4   g_bw4 [BATCH*9*HW2];            // bilinear corner weights
__device__ float    g_bts [BATCH*9*HW2];            // interior-masked weight sum
__device__ unsigned g_w2h[K2*C2];                   // conv2 W^T tf32 [ic*9+n][oc]
__device__ unsigned g_w4h[K4*C2];                   // conv4 W^T tf32
__device__ unsigned g_wOh[K4*32];                   // offsets W^T padded to 32 oc
__device__ float    g_p1s[C1*784], g_p1q[C1*784];   // BN1 per-block partials
__device__ float    g_p2s[C2*GB2], g_p2q[C2*GB2];   // BN2 per-block partials
__device__ float    g_scale1[C1], g_shift1[C1];
__device__ float    g_scale2[C2], g_shift2[C2];

// ---------------- helpers ----------------
__device__ __forceinline__ unsigned f2tf32(float f) {
    unsigned r; asm("cvt.rna.tf32.f32 %0, %1;" : "=r"(r) : "f"(f)); return r;
}
__device__ __forceinline__ void mma_tf32(float& d0, float& d1, float& d2, float& d3,
                                         unsigned a0, unsigned a1, unsigned a2, unsigned a3,
                                         unsigned b0, unsigned b1) {
    asm volatile("mma.sync.aligned.m16n8k8.row.col.f32.tf32.tf32.f32 "
                 "{%0,%1,%2,%3},{%4,%5,%6,%7},{%8,%9},{%0,%1,%2,%3};"
                 : "+f"(d0), "+f"(d1), "+f"(d2), "+f"(d3)
                 : "r"(a0), "r"(a1), "r"(a2), "r"(a3), "r"(b0), "r"(b1));
}
__device__ __forceinline__ void cp16(void* dst, const void* src) {
    unsigned d = (unsigned)__cvta_generic_to_shared(dst);
    asm volatile("cp.async.cg.shared.global [%0], [%1], 16;" :: "r"(d), "l"(src));
}
__device__ __forceinline__ void cp_commit() { asm volatile("cp.async.commit_group;"); }
__device__ __forceinline__ void cp_wait0()  { asm volatile("cp.async.wait_group 0;" ::: "memory"); }

// ---------------- weight transpose + tf32 round ----------------
__global__ void __launch_bounds__(256)
split_w_kernel(const float* __restrict__ w, unsigned* __restrict__ wh,
               int C_in, int C_out)
{
    int idx = blockIdx.x * 256 + threadIdx.x;
    int total = C_out * C_in * 9;
    if (idx >= total) return;
    int oc = idx % C_out;
    int r  = idx / C_out;
    int ic = r / 9, n = r % 9;
    wh[idx] = f2tf32(w[((size_t)oc*C_in + ic)*9 + n]);
}

__global__ void __launch_bounds__(256)
split_w_pad_kernel(const float* __restrict__ w, unsigned* __restrict__ wh)
{
    int idx = blockIdx.x * 256 + threadIdx.x;
    int total = K4 * 32;
    if (idx >= total) return;
    int oc = idx % 32;
    int r  = idx / 32;
    int ic = r / 9, n = r % 9;
    float v = (oc < COFF) ? w[((size_t)oc*C2 + ic)*9 + n] : 0.f;
    wh[idx] = f2tf32(v);
}

// ---------------- conv1 fused: conv + bias + relu + BN1 partials + 2x2 pool ----------------
__global__ void __launch_bounds__(128)
conv1_fused_kernel(const float* __restrict__ x, const float* __restrict__ wgt,
                   const float* __restrict__ bias)
{
    __shared__ float s_in[3][18][18];
    __shared__ float s_w[16][3][9];
    __shared__ float s_red[2][16][4];

    const int tileX  = (blockIdx.x % 14) * 16;
    const int tileY  = (blockIdx.x / 14) * 16;
    const int ocBase = blockIdx.y * 16;
    const int b      = blockIdx.z;
    const int tid    = threadIdx.x;
    const int tx     = tid & 15;
    const int ty     = tid >> 4;

    for (int e = tid; e < 3*18*18; e += 128) {
        int ic = e / 324;
        int r  = (e / 18) % 18;
        int c  = e % 18;
        int gy = tileY + r - 1, gx = tileX + c - 1;
        float v = 0.f;
        if (gy >= 0 && gy < H1 && gx >= 0 && gx < W1)
            v = x[(((size_t)b*3 + ic)*H1 + gy)*W1 + gx];
        s_in[ic][r][c] = v;
    }
    for (int e = tid; e < 16*27; e += 128) {
        int oc = e / 27, r = e % 27;
        int ic = r / 9, k = r % 9;
        s_w[oc][ic][k] = wgt[((size_t)(ocBase+oc)*3 + ic)*9 + k];
    }
    __syncthreads();

    float acc0[16], acc1[16];
#pragma unroll
    for (int i = 0; i < 16; i++) { acc0[i] = 0.f; acc1[i] = 0.f; }
    const int y0 = ty * 2;
#pragma unroll
    for (int ic = 0; ic < 3; ic++) {
        float r[4][3];
#pragma unroll
        for (int rr = 0; rr < 4; rr++)
#pragma unroll
            for (int cc = 0; cc < 3; cc++)
                r[rr][cc] = s_in[ic][y0+rr][tx+cc];
#pragma unroll
        for (int oc = 0; oc < 16; oc++) {
            float a0 = acc0[oc], a1 = acc1[oc];
#pragma unroll
            for (int k = 0; k < 9; k++) {
                float wv = s_w[oc][ic][k];
                a0 = fmaf(r[k/3  ][k%3], wv, a0);
                a1 = fmaf(r[k/3+1][k%3], wv, a1);
            }
            acc0[oc] = a0; acc1[oc] = a1;
        }
    }

    const int warp = tid >> 5, lane = tid & 31;
    const int prow = (tileY >> 1) + ty + 1;
    const int pcol = (tileX >> 1) + (tx >> 1) + 1;
    const int blkId = blockIdx.x + 196 * blockIdx.z;

#pragma unroll
    for (int oc = 0; oc < 16; oc++) {
        float bv = bias[ocBase + oc];
        float v0 = fmaxf(acc0[oc] + bv, 0.f);
        float v1 = fmaxf(acc1[oc] + bv, 0.f);
        float pv = v0 + v1;
        float po = pv + __shfl_xor_sync(0xffffffffu, pv, 1);
        if ((tx & 1) == 0)
            g_poolpad[(((size_t)b*C1 + ocBase + oc)*HP + prow)*WP + pcol] = 0.25f * po;
        float s = pv, q = v0*v0 + v1*v1;
#pragma unroll
        for (int o = 16; o; o >>= 1) {
            s += __shfl_down_sync(0xffffffffu, s, o);
            q += __shfl_down_sync(0xffffffffu, q, o);
        }
        if (lane == 0) { s_red[0][oc][warp] = s; s_red[1][oc][warp] = q; }
    }
    __syncthreads();
    if (tid < 16) {
        float S = s_red[0][tid][0] + s_red[0][tid][1] + s_red[0][tid][2] + s_red[0][tid][3];
        float Q = s_red[1][tid][0] + s_red[1][tid][1] + s_red[1][tid][2] + s_red[1][tid][3];
        g_p1s[(size_t)(ocBase + tid)*784 + blkId] = S;
        g_p1q[(size_t)(ocBase + tid)*784 + blkId] = Q;
    }
}

// ---------------- BN finalize ----------------
__global__ void __launch_bounds__(256)
bn_finalize_kernel(const float* __restrict__ ps, const float* __restrict__ pq,
                   const float* __restrict__ gamma, const float* __restrict__ beta,
                   float* __restrict__ scale, float* __restrict__ shift,
                   int nblk, float inv_count)
{
    const int c = blockIdx.x;
    const int tid = threadIdx.x;
    float s = 0.f, q = 0.f;
    for (int i = tid; i < nblk; i += 256) {
        s += ps[(size_t)c*nblk + i];
        q += pq[(size_t)c*nblk + i];
    }
    __shared__ float sh[64];
#pragma unroll
    for (int o = 16; o; o >>= 1) {
        s += __shfl_down_sync(0xffffffffu, s, o);
        q += __shfl_down_sync(0xffffffffu, q, o);
    }
    int warp = tid >> 5, lane = tid & 31;
    if (lane == 0) { sh[warp] = s; sh[32+warp] = q; }
    __syncthreads();
    if (warp == 0) {
        s = (lane < 8) ? sh[lane]    : 0.f;
        q = (lane < 8) ? sh[32+lane] : 0.f;
#pragma unroll
        for (int o = 4; o; o >>= 1) {
            s += __shfl_down_sync(0xffffffffu, s, o);
            q += __shfl_down_sync(0xffffffffu, q, o);
        }
        if (lane == 0) {
            float mean = s * inv_count;
            float var  = q * inv_count - mean*mean;
            float inv  = rsqrtf(var + 1e-5f);
            float sc   = gamma[c] * inv;
            scale[c] = sc;
            shift[c] = beta[c] - mean * sc;
        }
    }
}

// ---------------- conv2 im2col with BN1 fold -> g_x2 (tf32-rounded) ----------------
__global__ void __launch_bounds__(256)
x2col_kernel()
{
    const int hw = blockIdx.x * 256 + threadIdx.x;
    const int r  = blockIdx.y;                       // 0..575
    const int b  = blockIdx.z;
    if (hw >= HW2) return;
    const int ic = r / 9, n = r % 9;
    const int h = hw / W2, w = hw - h*W2;
    const int hh = h + n/3, ww = w + n%3;
    float raw = g_poolpad[((size_t)(b*C1 + ic))*HWP + hh*WP + ww];
    float m = ((unsigned)(hh-1) < 112u && (unsigned)(ww-1) < 112u) ? 1.f : 0.f;
    float v = raw * g_scale1[ic] + m * g_shift1[ic];
    g_x2[((size_t)b*K2 + r)*HW2 + hw] = __uint_as_float(f2tf32(v));
}

// ---------------- bilinear params per (b, tap, px) ----------------
__global__ void __launch_bounds__(256)
bilin_params_kernel()
{
    int idx = blockIdx.x * 256 + threadIdx.x;
    if (idx >= BATCH*9*HW2) return;
    int hw = idx % HW2;
    int n  = (idx / HW2) % 9;
    int b  = idx / (9*HW2);
    int h = hw / W2, w = hw - h*W2;
    float ox = g_offs[((size_t)b*COFF + n)     * HW2 + hw];
    float oy = g_offs[((size_t)b*COFF + 9 + n) * HW2 + hw];
    float pX = (float)(h + 1) + (float)(n/3 - 1) + ox;
    float pY = (float)(w + 1) + (float)(n%3 - 1) + oy;
    float fx = floorf(pX), fy = floorf(pY);
    float qltx = fminf(fmaxf(fx,     0.f), (float)(HP-1));
    float qlty = fminf(fmaxf(fy,     0.f), (float)(WP-1));
    float qrbx = fminf(fmaxf(fx+1.f, 0.f), (float)(HP-1));
    float qrby = fminf(fmaxf(fy+1.f, 0.f), (float)(WP-1));
    bool mx = (pX < 1.f) || (pX > (float)(HP-2));
    bool my = (pY < 1.f) || (pY > (float)(WP-2));
    float pxc = fminf(fmaxf(mx ? fx : pX, 0.f), (float)(HP-1));
    float pyc = fminf(fmaxf(my ? fy : pY, 0.f), (float)(WP-1));
    float glt = (1.f + (qltx - pxc)) * (1.f + (qlty - pyc));
    float grb = (1.f - (qrbx - pxc)) * (1.f - (qrby - pyc));
    float glb = (1.f + (qltx - pxc)) * (1.f - (qrby - pyc));
    float grt = (1.f - (qrbx - pxc)) * (1.f + (qlty - pyc));
    int ix0 = (int)qltx, iy0 = (int)qlty;
    int ix1 = (int)qrbx, iy1 = (int)qrby;
    float m0 = ((unsigned)(ix0-1) < 112u && (unsigned)(iy0-1) < 112u) ? 1.f : 0.f;
    float m1 = ((unsigned)(ix1-1) < 112u && (unsigned)(iy1-1) < 112u) ? 1.f : 0.f;
    float m2 = ((unsigned)(ix0-1) < 112u && (unsigned)(iy1-1) < 112u) ? 1.f : 0.f;
    float m3 = ((unsigned)(ix1-1) < 112u && (unsigned)(iy0-1) < 112u) ? 1.f : 0.f;
    g_bxy[idx] = (unsigned)ix0 | ((unsigned)iy0 << 8) | ((unsigned)ix1 << 16) | ((unsigned)iy1 << 24);
    g_bw4[idx] = make_float4(glt, grb, glb, grt);
    g_bts[idx] = glt*m0 + grb*m1 + glb*m2 + grt*m3;
}

// ---------------- deform gather: bilinear + BN2 fold -> g_xoff (tf32-rounded) ----------------
__global__ void __launch_bounds__(256)
xoff_kernel()
{
    __shared__ float s_s[C2], s_t[C2];
    const int tid = threadIdx.x;
    const int hw  = blockIdx.x * 256 + tid;
    const int n   = blockIdx.y;
    const int b   = blockIdx.z;
    if (tid < C2) { s_s[tid] = g_scale2[tid]; s_t[tid] = g_shift2[tid]; }
    __syncthreads();
    if (hw >= HW2) return;

    const int idx = (b*9 + n)*HW2 + hw;
    unsigned xy = g_bxy[idx];
    float4 bw   = g_bw4[idx];
    float  ts   = g_bts[idx];
    int ix0 = xy & 255, iy0 = (xy >> 8) & 255, ix1 = (xy >> 16) & 255, iy1 = xy >> 24;
    int i00 = ix0*WP + iy0;
    int i11 = ix1*WP + iy1;
    int i01 = ix0*WP + iy1;
    int i10 = ix1*WP + iy0;

    const float* base = g_h2pad + (size_t)b*C2*HWP;
    float* outp = g_xoff + ((size_t)b*K4 + n)*HW2 + hw;
#pragma unroll 4
    for (int ic = 0; ic < C2; ic++) {
        const float* plane = base + (size_t)ic*HWP;
        float raw = bw.x * __ldg(plane + i00)
                  + bw.y * __ldg(plane + i11)
                  + bw.z * __ldg(plane + i01)
                  + bw.w * __ldg(plane + i10);
        float v = raw * s_s[ic] + ts * s_t[ic];
        outp[(size_t)ic*9*HW2] = __uint_as_float(f2tf32(v));
    }
}

// ---------------- double-buffered 1x-tf32 MMA GEMM: 128px x 128oc, kchunk=32 ----------------
template<int NCHUNK, bool CONV2EPI>
__global__ void __launch_bounds__(256, 2)
gemm1x_kernel(const float* __restrict__ X, const unsigned* __restrict__ Wh,
              const float* __restrict__ bias, float* __restrict__ out)
{
    extern __shared__ unsigned smem_u[];
    const int SB = 32*136;   // 4352 words per stage buffer

    const int tid = threadIdx.x;
    const int blk = blockIdx.x;
    const int b   = blk / NT128;
    const int hw0 = (blk % NT128) * 128;
    const int lane = tid & 31, wid = tid >> 5;
    const int g = lane >> 2, t4 = lane & 3;

    const float* Xb = X + (size_t)b*(NCHUNK*32)*HW2 + hw0;

    // chunk loader: 32 K-rows of X (128 px) + 32 K-rows of W (128 oc)
    auto load_chunk = [&](int c, int buf) {
        const int k0 = c * 32;
        unsigned* sx = smem_u + buf*SB;
        unsigned* sw = smem_u + 2*SB + buf*SB;
        const uint4* h4 = (const uint4*)(Wh + (size_t)k0*C2);
        for (int e = tid; e < 1024; e += 256) {
            int row = e >> 5, cc = e & 31;
            cp16(sx + row*136 + cc*4, Xb + (size_t)(k0+row)*HW2 + cc*4);
            cp16(sw + row*136 + cc*4, h4 + e);
        }
        cp_commit();
    };

    load_chunk(0, 0);
    float acc[16][4] = {};

    for (int c = 0; c < NCHUNK; c++) {
        const int buf = c & 1;
        cp_wait0();
        __syncthreads();
        if (c + 1 < NCHUNK) load_chunk(c + 1, buf ^ 1);

        const unsigned* sx = smem_u + buf*SB;
        const unsigned* sw = smem_u + 2*SB + buf*SB;
#pragma unroll
        for (int ks = 0; ks < 4; ks++) {
            const unsigned* xp = sx + (ks*8 + t4)*136 + wid*16 + g;
            unsigned a0 = xp[0], a1 = xp[8], a2 = xp[4*136], a3 = xp[4*136+8];
            const unsigned* wp = sw + (ks*8 + t4)*136 + g;
#pragma unroll
            for (int nt = 0; nt < 16; nt++) {
                unsigned b0 = wp[nt*8], b1 = wp[4*136 + nt*8];
                mma_tf32(acc[nt][0],acc[nt][1],acc[nt][2],acc[nt][3], a0,a1,a2,a3, b0,b1);
            }
        }
        __syncthreads();
    }

    const int p0 = hw0 + wid*16 + g;
    const int p1 = p0 + 8;

    if (CONV2EPI) {
        float* s_red = (float*)smem_u;    // [8][128][2] floats
        const int h0 = p0 / W2, w0 = p0 - h0*W2;
        const int h1 = p1 / W2, w1 = p1 - h1*W2;
#pragma unroll
        for (int nt = 0; nt < 16; nt++) {
            int oc0 = nt*8 + 2*t4;
            int oc1 = oc0 + 1;
            float b0v = bias[oc0], b1v = bias[oc1];
            float v00 = fmaxf(acc[nt][0] + b0v, 0.f);
            float v01 = fmaxf(acc[nt][1] + b1v, 0.f);
            float v10 = fmaxf(acc[nt][2] + b0v, 0.f);
            float v11 = fmaxf(acc[nt][3] + b1v, 0.f);
            out[(((size_t)b*C2 + oc0)*HP + h0+1)*WP + w0+1] = v00;
            out[(((size_t)b*C2 + oc1)*HP + h0+1)*WP + w0+1] = v01;
            out[(((size_t)b*C2 + oc0)*HP + h1+1)*WP + w1+1] = v10;
            out[(((size_t)b*C2 + oc1)*HP + h1+1)*WP + w1+1] = v11;
            float s0 = v00 + v10, q0 = v00*v00 + v10*v10;
            float s1 = v01 + v11, q1 = v01*v01 + v11*v11;
#pragma unroll
            for (int o = 4; o <= 16; o <<= 1) {
                s0 += __shfl_xor_sync(0xffffffffu, s0, o);
                q0 += __shfl_xor_sync(0xffffffffu, q0, o);
                s1 += __shfl_xor_sync(0xffffffffu, s1, o);
                q1 += __shfl_xor_sync(0xffffffffu, q1, o);
            }
            if (g == 0) {
                s_red[(wid*128 + oc0)*2 + 0] = s0;
                s_red[(wid*128 + oc0)*2 + 1] = q0;
                s_red[(wid*128 + oc1)*2 + 0] = s1;
                s_red[(wid*128 + oc1)*2 + 1] = q1;
            }
        }
        __syncthreads();
        if (tid < 128) {
            float S = 0.f, Q = 0.f;
#pragma unroll
            for (int w = 0; w < 8; w++) {
                S += s_red[(w*128 + tid)*2 + 0];
                Q += s_red[(w*128 + tid)*2 + 1];
            }
            g_p2s[(size_t)tid*GB2 + blk] = S;
            g_p2q[(size_t)tid*GB2 + blk] = Q;
        }
    } else {
#pragma unroll
        for (int nt = 0; nt < 16; nt++) {
            int oc0 = nt*8 + 2*t4;
            int oc1 = oc0 + 1;
            out[((size_t)b*C2 + oc0)*HW2 + p0] = acc[nt][0];
            out[((size_t)b*C2 + oc1)*HW2 + p0] = acc[nt][1];
            out[((size_t)b*C2 + oc0)*HW2 + p1] = acc[nt][2];
            out[((size_t)b*C2 + oc1)*HW2 + p1] = acc[nt][3];
        }
    }
}

// ---------------- offsets conv: 1x-tf32 MMA, 128px x 32oc(pad 18), BN2 folded ----------------
__global__ void __launch_bounds__(256)
offs_mma_kernel(const float* __restrict__ bias)
{
    extern __shared__ unsigned smem_u[];
    unsigned* s_x  = smem_u;
    unsigned* s_w  = s_x + 72*XSO;
    float*    s_s  = (float*)(s_w + 72*WSO);
    float*    s_t  = s_s + C2;

    const int tid  = threadIdx.x;
    const int blk  = blockIdx.x;
    const int b    = blk / NOFF;
    const int hw0  = (blk % NOFF) * 128;
    const int lane = tid & 31, wid = tid >> 5;
    const int g    = lane >> 2, t4 = lane & 3;
    const int px0  = wid * 16;

    if (tid < C2) { s_s[tid] = g_scale2[tid]; s_t[tid] = g_shift2[tid]; }

    const float* inb = g_h2pad + (size_t)b*C2*HWP;
    float acc[4][4] = {};

    for (int ic0 = 0; ic0 < C2; ic0 += 8) {
        __syncthreads();
        {
            const uint4* sh4 = (const uint4*)(g_wOh + (size_t)ic0*9*32);
            for (int e = tid; e < 576; e += 256) {
                int kr = e >> 3, c4 = e & 7;
                cp16(s_w + kr*WSO + c4*4, sh4 + e);
            }
        }
        for (int e = tid; e < 9216; e += 256) {
            int r  = e >> 7, px = e & 127;
            int icr = r / 9, n = r - icr*9;
            int hw = hw0 + px;
            int h  = hw / W2, w = hw - h*W2;
            int hh = h + n/3, ww = w + n%3;
            float raw = inb[(size_t)(ic0+icr)*HWP + hh*WP + ww];
            float m = ((unsigned)(hh-1) < 112u && (unsigned)(ww-1) < 112u) ? 1.f : 0.f;
            float v = raw * s_s[ic0+icr] + m * s_t[ic0+icr];
            s_x[r*XSO + px] = f2tf32(v);
        }
        cp_commit(); cp_wait0();
        __syncthreads();

#pragma unroll
        for (int ks = 0; ks < 9; ks++) {
            const unsigned* xp = s_x + (ks*8 + t4)*XSO + px0 + g;
            unsigned a0 = xp[0], a1 = xp[8], a2 = xp[4*XSO], a3 = xp[4*XSO+8];
            const unsigned* wp = s_w + (ks*8 + t4)*WSO + g;
#pragma unroll
            for (int nt = 0; nt < 4; nt++) {
                unsigned b0 = wp[nt*8], b1 = wp[4*WSO + nt*8];
                mma_tf32(acc[nt][0],acc[nt][1],acc[nt][2],acc[nt][3], a0,a1,a2,a3, b0,b1);
            }
        }
    }

    const int p0 = hw0 + px0 + g, p1 = p0 + 8;
#pragma unroll
    for (int nt = 0; nt < 4; nt++) {
        int oc0 = nt*8 + 2*t4;
        int oc1 = oc0 + 1;
        if (oc0 < COFF) {
            float bv = bias[oc0];
            g_offs[((size_t)b*COFF + oc0)*HW2 + p0] = acc[nt][0] + bv;
            g_offs[((size_t)b*COFF + oc0)*HW2 + p1] = acc[nt][2] + bv;
        }
        if (oc1 < COFF) {
            float bv = bias[oc1];
            g_offs[((size_t)b*COFF + oc1)*HW2 + p0] = acc[nt][1] + bv;
            g_offs[((size_t)b*COFF + oc1)*HW2 + p1] = acc[nt][3] + bv;
        }
    }
}

// ---------------- launch ----------------
extern "C" void kernel_launch(void* const* d_in, const int* in_sizes, int n_in,
                              void* d_out, int out_size)
{
    const float* x       = (const float*)d_in[0];
    const float* conv1_w = (const float*)d_in[1];
    const float* conv1_b = (const float*)d_in[2];
    const float* bn1_g   = (const float*)d_in[3];
    const float* bn1_b   = (const float*)d_in[4];
    const float* conv2_w = (const float*)d_in[5];
    const float* conv2_b = (const float*)d_in[6];
    const float* bn2_g   = (const float*)d_in[7];
    const float* bn2_b   = (const float*)d_in[8];
    const float* off_w   = (const float*)d_in[9];
    const float* off_b   = (const float*)d_in[10];
    const float* conv4_w = (const float*)d_in[11];
    float* out = (float*)d_out;

    float *p_s1, *p_t1, *p_s2, *p_t2, *p_h2pad, *p_x2, *p_xoff;
    float *p_p1s, *p_p1q, *p_p2s, *p_p2q;
    unsigned *p_w2h, *p_w4h, *p_wOh;
    cudaGetSymbolAddress((void**)&p_s1,    g_scale1);
    cudaGetSymbolAddress((void**)&p_t1,    g_shift1);
    cudaGetSymbolAddress((void**)&p_s2,    g_scale2);
    cudaGetSymbolAddress((void**)&p_t2,    g_shift2);
    cudaGetSymbolAddress((void**)&p_h2pad, g_h2pad);
    cudaGetSymbolAddress((void**)&p_x2,    g_x2);
    cudaGetSymbolAddress((void**)&p_xoff,  g_xoff);
    cudaGetSymbolAddress((void**)&p_p1s,   g_p1s);
    cudaGetSymbolAddress((void**)&p_p1q,   g_p1q);
    cudaGetSymbolAddress((void**)&p_p2s,   g_p2s);
    cudaGetSymbolAddress((void**)&p_p2q,   g_p2q);
    cudaGetSymbolAddress((void**)&p_w2h,   g_w2h);
    cudaGetSymbolAddress((void**)&p_w4h,   g_w4h);
    cudaGetSymbolAddress((void**)&p_wOh,   g_wOh);

    const int SMEM_GEMM = 4 * 32 * 136 * 4;                    // 69632 B -> 2 CTAs/SM
    const int SMEM_OFFS = (72*XSO + 72*WSO) * 4 + 2*C2*4;
    cudaFuncSetAttribute(gemm1x_kernel<18, true>,
                         cudaFuncAttributeMaxDynamicSharedMemorySize, SMEM_GEMM);
    cudaFuncSetAttribute(gemm1x_kernel<36, false>,
                         cudaFuncAttributeMaxDynamicSharedMemorySize, SMEM_GEMM);
    cudaFuncSetAttribute(offs_mma_kernel,
                         cudaFuncAttributeMaxDynamicSharedMemorySize, SMEM_OFFS);

    // 0) weight preprocessing (tf32 round + transpose)
    split_w_kernel<<<(C2*C1*9 + 255)/256, 256>>>(conv2_w, p_w2h, C1, C2);
    split_w_kernel<<<(C2*C2*9 + 255)/256, 256>>>(conv4_w, p_w4h, C2, C2);
    split_w_pad_kernel<<<(K4*32 + 255)/256, 256>>>(off_w, p_wOh);

    // 1) conv1 + bias + relu + BN1 partials + 2x2 pool
    {
        dim3 grid(196, 4, BATCH);
        conv1_fused_kernel<<<grid, 128>>>(x, conv1_w, conv1_b);
    }
    // 2) BN1 finalize
    bn_finalize_kernel<<<C1, 256>>>(p_p1s, p_p1q, bn1_g, bn1_b, p_s1, p_t1,
                                    784, 1.0f/(float)(BATCH*H1*W1));
    // 3) conv2 im2col (BN1 folded)
    {
        dim3 grid(49, K2, BATCH);
        x2col_kernel<<<grid, 256>>>();
    }
    // 4) conv2 GEMM -> raw padded h2 + BN2 partials
    gemm1x_kernel<18, true><<<GB2, 256, SMEM_GEMM>>>(p_x2, p_w2h, conv2_b, p_h2pad);
    // 5) BN2 finalize
    bn_finalize_kernel<<<C2, 256>>>(p_p2s, p_p2q, bn2_g, bn2_b, p_s2, p_t2,
                                    GB2, 1.0f/(float)(BATCH*HW2));
    // 6) offsets conv (BN2 folded in gather)
    offs_mma_kernel<<<BATCH*NOFF, 256, SMEM_OFFS>>>(off_b);
    // 7) bilinear params
    bilin_params_kernel<<<(BATCH*9*HW2 + 255)/256, 256>>>();
    // 8) deform gather (BN2 folded) -> g_xoff
    {
        dim3 grid(49, 9, BATCH);
        xoff_kernel<<<grid, 256>>>();
    }
    // 9) deform GEMM -> d_out
    gemm1x_kernel<36, false><<<GB2, 256, SMEM_GEMM>>>(p_xoff, p_w4h, nullptr, out);
}